// round 1
// baseline (speedup 1.0000x reference)
#include <cuda_runtime.h>
#include <cstdint>

#define NN 100000
#define EE 600000
#define FF 512
#define HH 256
#define HG 128   // H2

// ---------------- scratch (static __device__ — no allocations) ----------------
__device__ float g_XW1[(size_t)NN * HH];
__device__ float g_XW2[(size_t)NN * HH];
__device__ float g_X0 [(size_t)NN * HH];
__device__ float g_G1 [(size_t)NN * HH];
__device__ float g_MEAN[(size_t)NN * HH];   // also reused as MLP hidden T [N,128]
__device__ float g_A1 [(size_t)NN * HG];
__device__ float g_dis1[NN], g_dis2[NN], g_inv1[NN], g_inv2[NN];
__device__ int   g_deg1[NN], g_deg2[NN];
__device__ int   g_rp1[NN + 1], g_rp2[NN + 1];
__device__ int   g_cur1[NN + 1], g_cur2[NN + 1];
__device__ int   g_col1[EE], g_col2[EE];
__device__ float g_part[25000];

// ---------------- small utility kernels ----------------
__global__ void k_zero_int(int* p, int n) {
    int i = blockIdx.x * blockDim.x + threadIdx.x;
    if (i < n) p[i] = 0;
}

__global__ void k_copy_int(int* dst, const int* src, int n) {
    int i = blockIdx.x * blockDim.x + threadIdx.x;
    if (i < n) dst[i] = src[i];
}

__global__ void k_deg(const int* __restrict__ dst, int* __restrict__ deg) {
    int e = blockIdx.x * blockDim.x + threadIdx.x;
    if (e < EE) atomicAdd(&deg[dst[e]], 1);
}

// single-block exclusive scan of deg[0..n) -> rp[0..n]
__global__ void k_scan(const int* __restrict__ deg, int* __restrict__ rp, int n) {
    __shared__ int s[1024];
    int t = threadIdx.x;
    int chunk = (n + 1023) >> 10;
    int b = t * chunk;
    int e = b + chunk; if (e > n) e = n;
    int local = 0;
    for (int i = b; i < e && i < n; i++) local += deg[i];
    s[t] = local;
    __syncthreads();
    for (int off = 1; off < 1024; off <<= 1) {
        int v = (t >= off) ? s[t - off] : 0;
        __syncthreads();
        s[t] += v;
        __syncthreads();
    }
    int run = (t == 0) ? 0 : s[t - 1];
    for (int i = b; i < e && i < n; i++) { rp[i] = run; run += deg[i]; }
    if (t == 1023) rp[n] = s[1023];
}

__global__ void k_disinv(const int* __restrict__ deg, float* __restrict__ dis,
                         float* __restrict__ inv) {
    int i = blockIdx.x * blockDim.x + threadIdx.x;
    if (i < NN) {
        float d = (float)deg[i];
        dis[i] = rsqrtf(d + 1.0f);          // self-loop adds 1 to degree
        inv[i] = 1.0f / fmaxf(d, 1.0f);     // SAGE mean denominator
    }
}

__global__ void k_place(const int* __restrict__ src, const int* __restrict__ dst,
                        int* __restrict__ cur, int* __restrict__ col) {
    int e = blockIdx.x * blockDim.x + threadIdx.x;
    if (e < EE) {
        int d = dst[e];
        int p = atomicAdd(&cur[d], 1);
        col[p] = src[e];
    }
}

// ---------------- SGEMM: C[N,M] = A[N,K] @ W[K,M]  (+C) (+bias) (relu) ----------------
// BM=BN=128, BK=16, 256 threads, 8x8 register tile
__global__ void __launch_bounds__(256)
k_sgemm(const float* __restrict__ A, const float* __restrict__ W,
        float* __restrict__ C, int K, int M,
        const float* __restrict__ bias, int accflag, int reluflag) {
    __shared__ __align__(16) float As[16][132];  // [kk][r], padded
    __shared__ __align__(16) float Ws[16][128];  // [kk][c]

    const int tid = threadIdx.x;
    const int tx = tid & 15, ty = tid >> 4;
    const int rowBase = blockIdx.y * 128;
    const int row0 = rowBase + ty * 8;
    const int col0 = blockIdx.x * 128 + tx * 8;

    float acc[8][8];
#pragma unroll
    for (int i = 0; i < 8; i++)
#pragma unroll
        for (int j = 0; j < 8; j++) acc[i][j] = 0.0f;

    for (int k0 = 0; k0 < K; k0 += 16) {
#pragma unroll
        for (int i = 0; i < 8; i++) {
            int idx = tid + i * 256;          // 0..2047
            int r = idx >> 4, kk = idx & 15;
            int gr = rowBase + r;
            As[kk][r] = (gr < NN) ? A[(size_t)gr * K + k0 + kk] : 0.0f;
        }
#pragma unroll
        for (int i = 0; i < 8; i++) {
            int idx = tid + i * 256;
            int kk = idx >> 7, c = idx & 127;
            Ws[kk][c] = W[(size_t)(k0 + kk) * M + blockIdx.x * 128 + c];
        }
        __syncthreads();
#pragma unroll
        for (int kk = 0; kk < 16; kk++) {
            float a[8], w[8];
            *(float4*)&a[0] = *(const float4*)&As[kk][ty * 8];
            *(float4*)&a[4] = *(const float4*)&As[kk][ty * 8 + 4];
            *(float4*)&w[0] = *(const float4*)&Ws[kk][tx * 8];
            *(float4*)&w[4] = *(const float4*)&Ws[kk][tx * 8 + 4];
#pragma unroll
            for (int i = 0; i < 8; i++)
#pragma unroll
                for (int j = 0; j < 8; j++) acc[i][j] += a[i] * w[j];
        }
        __syncthreads();
    }

#pragma unroll
    for (int i = 0; i < 8; i++) {
        int r = row0 + i;
        if (r < NN) {
            size_t ro = (size_t)r * M;
#pragma unroll
            for (int j = 0; j < 8; j++) {
                int c = col0 + j;
                float v = acc[i][j];
                if (accflag) v += C[ro + c];
                if (bias) v += bias[c];
                if (reluflag) v = fmaxf(v, 0.0f);
                C[ro + c] = v;
            }
        }
    }
}

// ---------------- GCN aggregation (warp per node, gather over CSR) ----------------
// mode 0: X0 = relu(out)                      (graph 1)
// mode 1: X0 += relu(out); G1 = relu(out)+out (graph 2)
__global__ void k_gcn(const float* __restrict__ xw, const int* __restrict__ rp,
                      const int* __restrict__ col, const float* __restrict__ dis,
                      const float* __restrict__ bias, int mode) {
    int node = blockIdx.x * 8 + (threadIdx.x >> 5);
    int lane = threadIdx.x & 31;
    if (node >= NN) return;

    const float4* xw4 = (const float4*)xw;
    float acc[8] = {0, 0, 0, 0, 0, 0, 0, 0};
    int e0 = rp[node], e1 = rp[node + 1];
    for (int e = e0; e < e1; e++) {
        int s = col[e];
        float ds = dis[s];
        float4 v0 = xw4[(size_t)s * 64 + 2 * lane];
        float4 v1 = xw4[(size_t)s * 64 + 2 * lane + 1];
        acc[0] += v0.x * ds; acc[1] += v0.y * ds; acc[2] += v0.z * ds; acc[3] += v0.w * ds;
        acc[4] += v1.x * ds; acc[5] += v1.y * ds; acc[6] += v1.z * ds; acc[7] += v1.w * ds;
    }
    float di = dis[node];
    float dii = di * di;
    float4 s0 = xw4[(size_t)node * 64 + 2 * lane];
    float4 s1 = xw4[(size_t)node * 64 + 2 * lane + 1];
    const float4* b4 = (const float4*)bias;
    float4 bb0 = b4[2 * lane], bb1 = b4[2 * lane + 1];

    float v[8];
    v[0] = acc[0] * di + s0.x * dii + bb0.x;
    v[1] = acc[1] * di + s0.y * dii + bb0.y;
    v[2] = acc[2] * di + s0.z * dii + bb0.z;
    v[3] = acc[3] * di + s0.w * dii + bb0.w;
    v[4] = acc[4] * di + s1.x * dii + bb1.x;
    v[5] = acc[5] * di + s1.y * dii + bb1.y;
    v[6] = acc[6] * di + s1.z * dii + bb1.z;
    v[7] = acc[7] * di + s1.w * dii + bb1.w;

    size_t o = (size_t)node * 64 + 2 * lane;
    float4* X04 = (float4*)g_X0;
    if (mode == 0) {
        float4 r0, r1;
        r0.x = fmaxf(v[0], 0.f); r0.y = fmaxf(v[1], 0.f); r0.z = fmaxf(v[2], 0.f); r0.w = fmaxf(v[3], 0.f);
        r1.x = fmaxf(v[4], 0.f); r1.y = fmaxf(v[5], 0.f); r1.z = fmaxf(v[6], 0.f); r1.w = fmaxf(v[7], 0.f);
        X04[o] = r0; X04[o + 1] = r1;
    } else {
        float r[8];
#pragma unroll
        for (int u = 0; u < 8; u++) r[u] = fmaxf(v[u], 0.f);
        float4 xa = X04[o], xb = X04[o + 1];
        xa.x += r[0]; xa.y += r[1]; xa.z += r[2]; xa.w += r[3];
        xb.x += r[4]; xb.y += r[5]; xb.z += r[6]; xb.w += r[7];
        X04[o] = xa; X04[o + 1] = xb;
        float4* G14 = (float4*)g_G1;
        float4 ga, gb;
        ga.x = r[0] + v[0]; ga.y = r[1] + v[1]; ga.z = r[2] + v[2]; ga.w = r[3] + v[3];
        gb.x = r[4] + v[4]; gb.y = r[5] + v[5]; gb.z = r[6] + v[6]; gb.w = r[7] + v[7];
        G14[o] = ga; G14[o + 1] = gb;
    }
}

// ---------------- SAGE mean aggregation (warp per node) -> g_MEAN ----------------
__global__ void k_sage(const float* __restrict__ feat, const int* __restrict__ rp,
                       const int* __restrict__ col, const float* __restrict__ inv) {
    int node = blockIdx.x * 8 + (threadIdx.x >> 5);
    int lane = threadIdx.x & 31;
    if (node >= NN) return;

    const float4* f4 = (const float4*)feat;
    float acc[8] = {0, 0, 0, 0, 0, 0, 0, 0};
    int e0 = rp[node], e1 = rp[node + 1];
    for (int e = e0; e < e1; e++) {
        int s = col[e];
        float4 v0 = f4[(size_t)s * 64 + 2 * lane];
        float4 v1 = f4[(size_t)s * 64 + 2 * lane + 1];
        acc[0] += v0.x; acc[1] += v0.y; acc[2] += v0.z; acc[3] += v0.w;
        acc[4] += v1.x; acc[5] += v1.y; acc[6] += v1.z; acc[7] += v1.w;
    }
    float ic = inv[node];
    size_t o = (size_t)node * 64 + 2 * lane;
    float4* m4 = (float4*)g_MEAN;
    float4 a, b;
    a.x = acc[0] * ic; a.y = acc[1] * ic; a.z = acc[2] * ic; a.w = acc[3] * ic;
    b.x = acc[4] * ic; b.y = acc[5] * ic; b.z = acc[6] * ic; b.w = acc[7] * ic;
    m4[o] = a; m4[o + 1] = b;
}

// ---------------- LayerNorm + final dot, warp per row, block partials ----------------
__device__ __forceinline__ float warp_sum(float v) {
#pragma unroll
    for (int o = 16; o; o >>= 1) v += __shfl_xor_sync(0xffffffffu, v, o);
    return v;
}

__global__ void k_lndot(const float* __restrict__ T, const float* __restrict__ lnw,
                        const float* __restrict__ lnb, const float* __restrict__ wm2,
                        const float* __restrict__ bm2, int poff) {
    __shared__ float ws[8];
    int wid = threadIdx.x >> 5, lane = threadIdx.x & 31;
    int row = blockIdx.x * 8 + wid;
    float y = 0.0f;
    if (row < NN) {
        float4 t = ((const float4*)T)[(size_t)row * 32 + lane];
        float sum = t.x + t.y + t.z + t.w;
        float sq = t.x * t.x + t.y * t.y + t.z * t.z + t.w * t.w;
        sum = warp_sum(sum);
        sq = warp_sum(sq);
        float mu = sum * (1.0f / 128.0f);
        float var = sq * (1.0f / 128.0f) - mu * mu;
        float rs = rsqrtf(var + 1e-5f);
        float4 w = ((const float4*)lnw)[lane];
        float4 b = ((const float4*)lnb)[lane];
        float4 m = ((const float4*)wm2)[lane];
        float p = ((t.x - mu) * rs * w.x + b.x) * m.x
                + ((t.y - mu) * rs * w.y + b.y) * m.y
                + ((t.z - mu) * rs * w.z + b.z) * m.z
                + ((t.w - mu) * rs * w.w + b.w) * m.w;
        p = warp_sum(p);
        y = p + bm2[0];
    }
    if (lane == 0) ws[wid] = y;
    __syncthreads();
    if (threadIdx.x == 0) {
        float s = 0;
#pragma unroll
        for (int i = 0; i < 8; i++) s += ws[i];
        g_part[poff + blockIdx.x] = s;
    }
}

__global__ void k_final(float* out) {
    __shared__ float s[1024];
    int t = threadIdx.x;
    float v = 0;
    for (int i = t; i < 25000; i += 1024) v += g_part[i];
    s[t] = v;
    __syncthreads();
    for (int off = 512; off; off >>= 1) {
        if (t < off) s[t] += s[t + off];
        __syncthreads();
    }
    if (t == 0) out[0] = s[0] * (1.0f / (2.0f * (float)NN));
}

// ---------------- host ----------------
static void* symaddr(const void* s) {
    void* p = nullptr;
    cudaGetSymbolAddress(&p, s);
    return p;
}

extern "C" void kernel_launch(void* const* d_in, const int* in_sizes, int n_in,
                              void* d_out, int out_size) {
    const float* x   = (const float*)d_in[0];
    const float* x1  = (const float*)d_in[1];
    const int*   ei  = (const int*)d_in[2];
    const int*   ei1 = (const int*)d_in[3];
    const float* Wg1 = (const float*)d_in[4];
    const float* bg1 = (const float*)d_in[5];
    const float* Wg2 = (const float*)d_in[6];
    const float* bg2 = (const float*)d_in[7];
    const float* Wl1 = (const float*)d_in[8];
    const float* bl1 = (const float*)d_in[9];
    const float* Wr1 = (const float*)d_in[10];
    const float* Wl2 = (const float*)d_in[11];
    const float* bl2 = (const float*)d_in[12];
    const float* Wr2 = (const float*)d_in[13];
    const float* Wm1 = (const float*)d_in[14];
    const float* bm1 = (const float*)d_in[15];
    const float* lnw = (const float*)d_in[16];
    const float* lnb = (const float*)d_in[17];
    const float* Wm2 = (const float*)d_in[18];
    const float* bm2 = (const float*)d_in[19];

    const int* src1 = ei;
    const int* dst1 = ei + EE;
    const int* src2 = ei1;
    const int* dst2 = ei1 + EE;

    float* XW1  = (float*)symaddr(g_XW1);
    float* XW2  = (float*)symaddr(g_XW2);
    float* X0   = (float*)symaddr(g_X0);
    float* G1   = (float*)symaddr(g_G1);
    float* MEAN = (float*)symaddr(g_MEAN);
    float* A1   = (float*)symaddr(g_A1);
    float* dis1 = (float*)symaddr(g_dis1);
    float* dis2 = (float*)symaddr(g_dis2);
    float* inv1 = (float*)symaddr(g_inv1);
    float* inv2 = (float*)symaddr(g_inv2);
    int* deg1 = (int*)symaddr(g_deg1);
    int* deg2 = (int*)symaddr(g_deg2);
    int* rp1  = (int*)symaddr(g_rp1);
    int* rp2  = (int*)symaddr(g_rp2);
    int* cur1 = (int*)symaddr(g_cur1);
    int* cur2 = (int*)symaddr(g_cur2);
    int* col1 = (int*)symaddr(g_col1);
    int* col2 = (int*)symaddr(g_col2);

    const int TB = 256;
    const int gN = (NN + TB - 1) / TB;
    const int gE = (EE + TB - 1) / TB;

    // --- build CSR for both graphs ---
    k_zero_int<<<gN, TB>>>(deg1, NN);
    k_zero_int<<<gN, TB>>>(deg2, NN);
    k_deg<<<gE, TB>>>(dst1, deg1);
    k_deg<<<gE, TB>>>(dst2, deg2);
    k_scan<<<1, 1024>>>(deg1, rp1, NN);
    k_scan<<<1, 1024>>>(deg2, rp2, NN);
    k_disinv<<<gN, TB>>>(deg1, dis1, inv1);
    k_disinv<<<gN, TB>>>(deg2, dis2, inv2);
    k_copy_int<<<gN, TB>>>(cur1, rp1, NN);
    k_copy_int<<<gN, TB>>>(cur2, rp2, NN);
    k_place<<<gE, TB>>>(src1, dst1, cur1, col1);
    k_place<<<gE, TB>>>(src2, dst2, cur2, col2);

    // --- GCN layer: XW = x @ Wg ---
    dim3 gGcn(HH / 128, (NN + 127) / 128);
    k_sgemm<<<gGcn, 256>>>(x,  Wg1, XW1, FF, HH, nullptr, 0, 0);
    k_sgemm<<<gGcn, 256>>>(x1, Wg2, XW2, FF, HH, nullptr, 0, 0);

    const int gW = NN / 8;  // warp-per-node kernels
    k_gcn<<<gW, 256>>>(XW1, rp1, col1, dis1, bg1, 0);  // X0 = relu(gcn1)
    k_gcn<<<gW, 256>>>(XW2, rp2, col2, dis2, bg2, 1);  // X0 += relu(gcn2); G1 = relu+pre

    // --- branch A: SAGE(graph1, X0) -> MLP ---
    dim3 gSg(HG / 128, (NN + 127) / 128);
    k_sage<<<gW, 256>>>(X0, rp1, col1, inv1);                          // MEAN
    k_sgemm<<<gSg, 256>>>(MEAN, Wl1, A1, HH, HG, bl1, 0, 0);
    k_sgemm<<<gSg, 256>>>(X0,   Wr1, A1, HH, HG, nullptr, 1, 1);       // relu
    k_sgemm<<<gSg, 256>>>(A1,   Wm1, MEAN, HG, HG, bm1, 0, 0);         // T (reuse MEAN)
    k_lndot<<<gW, 256>>>(MEAN, lnw, lnb, Wm2, bm2, 0);

    // --- branch B: SAGE(graph2, G1) -> MLP ---
    k_sage<<<gW, 256>>>(G1, rp2, col2, inv2);                          // MEAN
    k_sgemm<<<gSg, 256>>>(MEAN, Wl2, A1, HH, HG, bl2, 0, 0);
    k_sgemm<<<gSg, 256>>>(G1,   Wr2, A1, HH, HG, nullptr, 1, 1);       // relu
    k_sgemm<<<gSg, 256>>>(A1,   Wm1, MEAN, HG, HG, bm1, 0, 0);         // T
    k_lndot<<<gW, 256>>>(MEAN, lnw, lnb, Wm2, bm2, NN / 8);

    k_final<<<1, 1024>>>((float*)d_out);
}

// round 3
// speedup vs baseline: 1.8677x; 1.8677x over previous
#include <cuda_runtime.h>
#include <cuda_bf16.h>
#include <cstdint>

#define NN 100000
#define EE 600000
#define FF 512
#define HH 256
#define HG 128   // H2

// ---------------- scratch (static __device__ — no allocations) ----------------
__device__ float g_XW1[(size_t)NN * HH];
__device__ float g_XW2[(size_t)NN * HH];
__device__ float g_X0 [(size_t)NN * HH];
__device__ float g_G1 [(size_t)NN * HH];
__device__ float g_MEAN[(size_t)NN * HH];   // also reused as MLP hidden T [N,128]
__device__ float g_A1 [(size_t)NN * HG];
__device__ float g_dis1[NN], g_dis2[NN], g_inv1[NN], g_inv2[NN];
__device__ int   g_deg1[NN], g_deg2[NN];
__device__ int   g_rp1[NN + 1], g_rp2[NN + 1];
__device__ int   g_cur1[NN + 1], g_cur2[NN + 1];
__device__ int   g_col1[EE], g_col2[EE];
__device__ float g_part[25000];

// pre-split, pre-transposed weights (bf16 hi/lo), layout WT[n*K + k]
#define OWG1 0
#define OWG2 131072
#define OWL1 262144
#define OWR1 294912
#define OWL2 327680
#define OWR2 360448
#define OWM1 393216
__device__ __nv_bfloat16 g_wth[409600];
__device__ __nv_bfloat16 g_wtl[409600];

// ---------------- weight split+transpose: WT[n*K+k] = split(W[k*M+n]) ----------------
__global__ void k_wt(const float* __restrict__ W, __nv_bfloat16* __restrict__ th,
                     __nv_bfloat16* __restrict__ tl, int K, int M) {
    int i = blockIdx.x * blockDim.x + threadIdx.x;
    if (i < K * M) {
        int k = i / M, n = i % M;
        float w = W[i];
        __nv_bfloat16 h = __float2bfloat16(w);
        th[(size_t)n * K + k] = h;
        tl[(size_t)n * K + k] = __float2bfloat16(w - __bfloat162float(h));
    }
}

// ---------------- MMA GEMM: C[NN,M] = A1@W1 (+ A2@W2) (+bias)(relu) ----------------
// A fp32 -> bf16 in-kernel; W pre-split bf16 hi+lo (2 MMA products).
// BM=128, BN=128, BK=32, 256 threads, double-buffered cp.async for W.
#define LDSB 80          // bytes per smem row (32 bf16 = 64B + 16B pad)
#define STG_A 10240      // 128 rows * 80B
#define OFF_A  0
#define OFF_BH 20480
#define OFF_BL 40960
#define SMEM_MMA 61440

__device__ __forceinline__ uint32_t sm2u32(const void* p) {
    return (uint32_t)__cvta_generic_to_shared(p);
}

__device__ __forceinline__ void cpa16(uint32_t dst, const void* src) {
    asm volatile("cp.async.ca.shared.global [%0], [%1], 16;"
                 :: "r"(dst), "l"(src));
}

__device__ __forceinline__ void mma_bf16(float* c, const uint32_t* a, const uint32_t* b) {
    asm volatile(
        "mma.sync.aligned.m16n8k16.row.col.f32.bf16.bf16.f32 "
        "{%0,%1,%2,%3}, {%4,%5,%6,%7}, {%8,%9}, {%0,%1,%2,%3};"
        : "+f"(c[0]), "+f"(c[1]), "+f"(c[2]), "+f"(c[3])
        : "r"(a[0]), "r"(a[1]), "r"(a[2]), "r"(a[3]), "r"(b[0]), "r"(b[1]));
}

__global__ void __launch_bounds__(256, 1)
k_mma(const float* __restrict__ A1p, const __nv_bfloat16* __restrict__ W1h,
      const __nv_bfloat16* __restrict__ W1l, int K1,
      const float* __restrict__ A2p, const __nv_bfloat16* __restrict__ W2h,
      const __nv_bfloat16* __restrict__ W2l, int K2,
      float* __restrict__ C, int M,
      const float* __restrict__ bias, int reluflag)
{
    extern __shared__ __align__(16) char smem[];
    const uint32_t sb = sm2u32(smem);
    const int tid = threadIdx.x;
    const int wid = tid >> 5, lane = tid & 31;
    const int warp_m = wid & 1, warp_n = wid >> 1;
    const int rowBase = blockIdx.y * 128;
    const int colBase = blockIdx.x * 128;

    const int n1 = K1 >> 5;
    const int n2 = A2p ? (K2 >> 5) : 0;
    const int total = n1 + n2;

    float acc[4][4][4];
#pragma unroll
    for (int i = 0; i < 4; i++)
#pragma unroll
        for (int j = 0; j < 4; j++)
#pragma unroll
            for (int q = 0; q < 4; q++) acc[i][j][q] = 0.0f;

    // thread's A-load mapping: row r, 16-col half
    const int a_r = tid >> 1;
    const int a_c = (tid & 1) * 16;

    uint32_t aregs[8];

    // select chunk
    auto pick = [&](int it, const float*& A, const __nv_bfloat16*& Wh,
                    const __nv_bfloat16*& Wl, int& K, int& k0) {
        if (it < n1) { A = A1p; Wh = W1h; Wl = W1l; K = K1; k0 = it << 5; }
        else         { A = A2p; Wh = W2h; Wl = W2l; K = K2; k0 = (it - n1) << 5; }
    };

    auto issueB = [&](int it, int stage) {
        const float* A; const __nv_bfloat16 *Wh, *Wl; int K, k0;
        pick(it, A, Wh, Wl, K, k0);
#pragma unroll
        for (int i = 0; i < 2; i++) {
            int idx = tid + i * 256;         // 0..511
            int n = idx >> 2, part = idx & 3;
            int gn = colBase + n;
            uint32_t d = sb + stage * STG_A + n * LDSB + part * 16;
            cpa16(OFF_BH + d, Wh + (size_t)gn * K + k0 + part * 8);
            cpa16(OFF_BL + d, Wl + (size_t)gn * K + k0 + part * 8);
        }
        asm volatile("cp.async.commit_group;");
    };

    auto loadA = [&](int it) {
        const float* A; const __nv_bfloat16 *Wh, *Wl; int K, k0;
        pick(it, A, Wh, Wl, K, k0);
        int gr = rowBase + a_r;
        const float* p = A + (size_t)gr * K + k0 + a_c;
#pragma unroll
        for (int j = 0; j < 4; j++) {
            float4 v = (gr < NN) ? *(const float4*)(p + 4 * j)
                                 : make_float4(0.f, 0.f, 0.f, 0.f);
            uint32_t lo = ((uint32_t)__bfloat16_as_ushort(__float2bfloat16(v.y)) << 16)
                        | __bfloat16_as_ushort(__float2bfloat16(v.x));
            uint32_t hi = ((uint32_t)__bfloat16_as_ushort(__float2bfloat16(v.w)) << 16)
                        | __bfloat16_as_ushort(__float2bfloat16(v.z));
            aregs[2 * j] = lo;
            aregs[2 * j + 1] = hi;
        }
    };

    auto storeA = [&](int stage) {
        uint32_t d = sb + OFF_A + stage * STG_A + a_r * LDSB + a_c * 2;
#pragma unroll
        for (int j = 0; j < 8; j++)
            asm volatile("st.shared.b32 [%0], %1;" :: "r"(d + 4 * j), "r"(aregs[j]));
    };

    auto compute = [&](int stage) {
#pragma unroll
        for (int ks = 0; ks < 2; ks++) {
            const int kk = ks * 16;
            uint32_t af[4][4];
#pragma unroll
            for (int mi = 0; mi < 4; mi++) {
                int row = warp_m * 64 + mi * 16 + (lane & 15);
                int kc = kk + ((lane >> 4) << 3);
                uint32_t ad = sb + OFF_A + stage * STG_A + row * LDSB + kc * 2;
                asm volatile("ldmatrix.sync.aligned.m8n8.x4.shared.b16 "
                             "{%0,%1,%2,%3}, [%4];"
                             : "=r"(af[mi][0]), "=r"(af[mi][1]),
                               "=r"(af[mi][2]), "=r"(af[mi][3]) : "r"(ad));
            }
            uint32_t bh[4][2], bl[4][2];
#pragma unroll
            for (int ni = 0; ni < 4; ni++) {
                int rn = warp_n * 32 + ni * 8 + (lane & 7);
                int kc = kk + ((lane >> 3) & 1) * 8;
                uint32_t off = stage * STG_A + rn * LDSB + kc * 2;
                asm volatile("ldmatrix.sync.aligned.m8n8.x2.shared.b16 {%0,%1}, [%2];"
                             : "=r"(bh[ni][0]), "=r"(bh[ni][1])
                             : "r"(sb + OFF_BH + off));
                asm volatile("ldmatrix.sync.aligned.m8n8.x2.shared.b16 {%0,%1}, [%2];"
                             : "=r"(bl[ni][0]), "=r"(bl[ni][1])
                             : "r"(sb + OFF_BL + off));
            }
#pragma unroll
            for (int mi = 0; mi < 4; mi++)
#pragma unroll
                for (int ni = 0; ni < 4; ni++) {
                    mma_bf16(acc[mi][ni], af[mi], bh[ni]);
                    mma_bf16(acc[mi][ni], af[mi], bl[ni]);
                }
        }
    };

    // prologue: chunk 0 -> stage 0
    issueB(0, 0);
    loadA(0);
    storeA(0);
    asm volatile("cp.async.wait_group 0;");
    __syncthreads();

    int stage = 0;
    for (int it = 0; it < total; ++it) {
        if (it + 1 < total) {
            issueB(it + 1, stage ^ 1);
            loadA(it + 1);
        }
        compute(stage);
        if (it + 1 < total) {
            storeA(stage ^ 1);
            asm volatile("cp.async.wait_group 0;");
        }
        __syncthreads();
        stage ^= 1;
    }

    // epilogue
    const int g = lane >> 2, tg = lane & 3;
#pragma unroll
    for (int mi = 0; mi < 4; mi++) {
#pragma unroll
        for (int ni = 0; ni < 4; ni++) {
            int col = colBase + warp_n * 32 + ni * 8 + tg * 2;
            float b0 = 0.f, b1 = 0.f;
            if (bias) { b0 = bias[col]; b1 = bias[col + 1]; }
            int row = rowBase + warp_m * 64 + mi * 16 + g;
            if (row < NN) {
                float2 v;
                v.x = acc[mi][ni][0] + b0;
                v.y = acc[mi][ni][1] + b1;
                if (reluflag) { v.x = fmaxf(v.x, 0.f); v.y = fmaxf(v.y, 0.f); }
                *(float2*)(C + (size_t)row * M + col) = v;
            }
            if (row + 8 < NN) {
                float2 v;
                v.x = acc[mi][ni][2] + b0;
                v.y = acc[mi][ni][3] + b1;
                if (reluflag) { v.x = fmaxf(v.x, 0.f); v.y = fmaxf(v.y, 0.f); }
                *(float2*)(C + (size_t)(row + 8) * M + col) = v;
            }
        }
    }
}

// ---------------- small utility kernels ----------------
__global__ void k_zero_int(int* p, int n) {
    int i = blockIdx.x * blockDim.x + threadIdx.x;
    if (i < n) p[i] = 0;
}

__global__ void k_copy_int(int* dst, const int* src, int n) {
    int i = blockIdx.x * blockDim.x + threadIdx.x;
    if (i < n) dst[i] = src[i];
}

__global__ void k_deg(const int* __restrict__ dst, int* __restrict__ deg) {
    int e = blockIdx.x * blockDim.x + threadIdx.x;
    if (e < EE) atomicAdd(&deg[dst[e]], 1);
}

__global__ void k_scan(const int* __restrict__ deg, int* __restrict__ rp, int n) {
    __shared__ int s[1024];
    int t = threadIdx.x;
    int chunk = (n + 1023) >> 10;
    int b = t * chunk;
    int e = b + chunk; if (e > n) e = n;
    int local = 0;
    for (int i = b; i < e && i < n; i++) local += deg[i];
    s[t] = local;
    __syncthreads();
    for (int off = 1; off < 1024; off <<= 1) {
        int v = (t >= off) ? s[t - off] : 0;
        __syncthreads();
        s[t] += v;
        __syncthreads();
    }
    int run = (t == 0) ? 0 : s[t - 1];
    for (int i = b; i < e && i < n; i++) { rp[i] = run; run += deg[i]; }
    if (t == 1023) rp[n] = s[1023];
}

__global__ void k_disinv(const int* __restrict__ deg, float* __restrict__ dis,
                         float* __restrict__ inv) {
    int i = blockIdx.x * blockDim.x + threadIdx.x;
    if (i < NN) {
        float d = (float)deg[i];
        dis[i] = rsqrtf(d + 1.0f);
        inv[i] = 1.0f / fmaxf(d, 1.0f);
    }
}

__global__ void k_place(const int* __restrict__ src, const int* __restrict__ dst,
                        int* __restrict__ cur, int* __restrict__ col) {
    int e = blockIdx.x * blockDim.x + threadIdx.x;
    if (e < EE) {
        int d = dst[e];
        int p = atomicAdd(&cur[d], 1);
        col[p] = src[e];
    }
}

// ---------------- GCN aggregation (warp per node, gather over CSR) ----------------
__global__ void k_gcn(const float* __restrict__ xw, const int* __restrict__ rp,
                      const int* __restrict__ col, const float* __restrict__ dis,
                      const float* __restrict__ bias, int mode) {
    int node = blockIdx.x * 8 + (threadIdx.x >> 5);
    int lane = threadIdx.x & 31;
    if (node >= NN) return;

    const float4* xw4 = (const float4*)xw;
    float acc[8] = {0, 0, 0, 0, 0, 0, 0, 0};
    int e0 = rp[node], e1 = rp[node + 1];
    for (int e = e0; e < e1; e++) {
        int s = col[e];
        float ds = dis[s];
        float4 v0 = xw4[(size_t)s * 64 + 2 * lane];
        float4 v1 = xw4[(size_t)s * 64 + 2 * lane + 1];
        acc[0] += v0.x * ds; acc[1] += v0.y * ds; acc[2] += v0.z * ds; acc[3] += v0.w * ds;
        acc[4] += v1.x * ds; acc[5] += v1.y * ds; acc[6] += v1.z * ds; acc[7] += v1.w * ds;
    }
    float di = dis[node];
    float dii = di * di;
    float4 s0 = xw4[(size_t)node * 64 + 2 * lane];
    float4 s1 = xw4[(size_t)node * 64 + 2 * lane + 1];
    const float4* b4 = (const float4*)bias;
    float4 bb0 = b4[2 * lane], bb1 = b4[2 * lane + 1];

    float v[8];
    v[0] = acc[0] * di + s0.x * dii + bb0.x;
    v[1] = acc[1] * di + s0.y * dii + bb0.y;
    v[2] = acc[2] * di + s0.z * dii + bb0.z;
    v[3] = acc[3] * di + s0.w * dii + bb0.w;
    v[4] = acc[4] * di + s1.x * dii + bb1.x;
    v[5] = acc[5] * di + s1.y * dii + bb1.y;
    v[6] = acc[6] * di + s1.z * dii + bb1.z;
    v[7] = acc[7] * di + s1.w * dii + bb1.w;

    size_t o = (size_t)node * 64 + 2 * lane;
    float4* X04 = (float4*)g_X0;
    if (mode == 0) {
        float4 r0, r1;
        r0.x = fmaxf(v[0], 0.f); r0.y = fmaxf(v[1], 0.f); r0.z = fmaxf(v[2], 0.f); r0.w = fmaxf(v[3], 0.f);
        r1.x = fmaxf(v[4], 0.f); r1.y = fmaxf(v[5], 0.f); r1.z = fmaxf(v[6], 0.f); r1.w = fmaxf(v[7], 0.f);
        X04[o] = r0; X04[o + 1] = r1;
    } else {
        float r[8];
#pragma unroll
        for (int u = 0; u < 8; u++) r[u] = fmaxf(v[u], 0.f);
        float4 xa = X04[o], xb = X04[o + 1];
        xa.x += r[0]; xa.y += r[1]; xa.z += r[2]; xa.w += r[3];
        xb.x += r[4]; xb.y += r[5]; xb.z += r[6]; xb.w += r[7];
        X04[o] = xa; X04[o + 1] = xb;
        float4* G14 = (float4*)g_G1;
        float4 ga, gb;
        ga.x = r[0] + v[0]; ga.y = r[1] + v[1]; ga.z = r[2] + v[2]; ga.w = r[3] + v[3];
        gb.x = r[4] + v[4]; gb.y = r[5] + v[5]; gb.z = r[6] + v[6]; gb.w = r[7] + v[7];
        G14[o] = ga; G14[o + 1] = gb;
    }
}

// ---------------- SAGE mean aggregation (warp per node) -> g_MEAN ----------------
__global__ void k_sage(const float* __restrict__ feat, const int* __restrict__ rp,
                       const int* __restrict__ col, const float* __restrict__ inv) {
    int node = blockIdx.x * 8 + (threadIdx.x >> 5);
    int lane = threadIdx.x & 31;
    if (node >= NN) return;

    const float4* f4 = (const float4*)feat;
    float acc[8] = {0, 0, 0, 0, 0, 0, 0, 0};
    int e0 = rp[node], e1 = rp[node + 1];
    for (int e = e0; e < e1; e++) {
        int s = col[e];
        float4 v0 = f4[(size_t)s * 64 + 2 * lane];
        float4 v1 = f4[(size_t)s * 64 + 2 * lane + 1];
        acc[0] += v0.x; acc[1] += v0.y; acc[2] += v0.z; acc[3] += v0.w;
        acc[4] += v1.x; acc[5] += v1.y; acc[6] += v1.z; acc[7] += v1.w;
    }
    float ic = inv[node];
    size_t o = (size_t)node * 64 + 2 * lane;
    float4* m4 = (float4*)g_MEAN;
    float4 a, b;
    a.x = acc[0] * ic; a.y = acc[1] * ic; a.z = acc[2] * ic; a.w = acc[3] * ic;
    b.x = acc[4] * ic; b.y = acc[5] * ic; b.z = acc[6] * ic; b.w = acc[7] * ic;
    m4[o] = a; m4[o + 1] = b;
}

// ---------------- LayerNorm + final dot, warp per row ----------------
__device__ __forceinline__ float warp_sum(float v) {
#pragma unroll
    for (int o = 16; o; o >>= 1) v += __shfl_xor_sync(0xffffffffu, v, o);
    return v;
}

__global__ void k_lndot(const float* __restrict__ T, const float* __restrict__ lnw,
                        const float* __restrict__ lnb, const float* __restrict__ wm2,
                        const float* __restrict__ bm2, int poff) {
    __shared__ float ws[8];
    int wid = threadIdx.x >> 5, lane = threadIdx.x & 31;
    int row = blockIdx.x * 8 + wid;
    float y = 0.0f;
    if (row < NN) {
        float4 t = ((const float4*)T)[(size_t)row * 32 + lane];
        float sum = t.x + t.y + t.z + t.w;
        float sq = t.x * t.x + t.y * t.y + t.z * t.z + t.w * t.w;
        sum = warp_sum(sum);
        sq = warp_sum(sq);
        float mu = sum * (1.0f / 128.0f);
        float var = sq * (1.0f / 128.0f) - mu * mu;
        float rs = rsqrtf(var + 1e-5f);
        float4 w = ((const float4*)lnw)[lane];
        float4 b = ((const float4*)lnb)[lane];
        float4 m = ((const float4*)wm2)[lane];
        float p = ((t.x - mu) * rs * w.x + b.x) * m.x
                + ((t.y - mu) * rs * w.y + b.y) * m.y
                + ((t.z - mu) * rs * w.z + b.z) * m.z
                + ((t.w - mu) * rs * w.w + b.w) * m.w;
        p = warp_sum(p);
        y = p + bm2[0];
    }
    if (lane == 0) ws[wid] = y;
    __syncthreads();
    if (threadIdx.x == 0) {
        float s = 0;
#pragma unroll
        for (int i = 0; i < 8; i++) s += ws[i];
        g_part[poff + blockIdx.x] = s;
    }
}

__global__ void k_final(float* out) {
    __shared__ float s[1024];
    int t = threadIdx.x;
    float v = 0;
    for (int i = t; i < 25000; i += 1024) v += g_part[i];
    s[t] = v;
    __syncthreads();
    for (int off = 512; off; off >>= 1) {
        if (t < off) s[t] += s[t + off];
        __syncthreads();
    }
    if (t == 0) out[0] = s[0] * (1.0f / (2.0f * (float)NN));
}

// ---------------- host ----------------
static void* symaddr(const void* s) {
    void* p = nullptr;
    cudaGetSymbolAddress(&p, s);
    return p;
}

extern "C" void kernel_launch(void* const* d_in, const int* in_sizes, int n_in,
                              void* d_out, int out_size) {
    const float* x   = (const float*)d_in[0];
    const float* x1  = (const float*)d_in[1];
    const int*   ei  = (const int*)d_in[2];
    const int*   ei1 = (const int*)d_in[3];
    const float* Wg1 = (const float*)d_in[4];
    const float* bg1 = (const float*)d_in[5];
    const float* Wg2 = (const float*)d_in[6];
    const float* bg2 = (const float*)d_in[7];
    const float* Wl1 = (const float*)d_in[8];
    const float* bl1 = (const float*)d_in[9];
    const float* Wr1 = (const float*)d_in[10];
    const float* Wl2 = (const float*)d_in[11];
    const float* bl2 = (const float*)d_in[12];
    const float* Wr2 = (const float*)d_in[13];
    const float* Wm1 = (const float*)d_in[14];
    const float* bm1 = (const float*)d_in[15];
    const float* lnw = (const float*)d_in[16];
    const float* lnb = (const float*)d_in[17];
    const float* Wm2 = (const float*)d_in[18];
    const float* bm2 = (const float*)d_in[19];

    const int* src1 = ei;
    const int* dst1 = ei + EE;
    const int* src2 = ei1;
    const int* dst2 = ei1 + EE;

    float* XW1  = (float*)symaddr(g_XW1);
    float* XW2  = (float*)symaddr(g_XW2);
    float* X0   = (float*)symaddr(g_X0);
    float* G1   = (float*)symaddr(g_G1);
    float* MEAN = (float*)symaddr(g_MEAN);
    float* A1   = (float*)symaddr(g_A1);
    float* dis1 = (float*)symaddr(g_dis1);
    float* dis2 = (float*)symaddr(g_dis2);
    float* inv1 = (float*)symaddr(g_inv1);
    float* inv2 = (float*)symaddr(g_inv2);
    int* deg1 = (int*)symaddr(g_deg1);
    int* deg2 = (int*)symaddr(g_deg2);
    int* rp1  = (int*)symaddr(g_rp1);
    int* rp2  = (int*)symaddr(g_rp2);
    int* cur1 = (int*)symaddr(g_cur1);
    int* cur2 = (int*)symaddr(g_cur2);
    int* col1 = (int*)symaddr(g_col1);
    int* col2 = (int*)symaddr(g_col2);
    __nv_bfloat16* wth = (__nv_bfloat16*)symaddr(g_wth);
    __nv_bfloat16* wtl = (__nv_bfloat16*)symaddr(g_wtl);

    const int TB = 256;
    const int gN = (NN + TB - 1) / TB;
    const int gE = (EE + TB - 1) / TB;

    // --- weight split+transpose (tiny) ---
    k_wt<<<(FF * HH + 255) / 256, 256>>>(Wg1, wth + OWG1, wtl + OWG1, FF, HH);
    k_wt<<<(FF * HH + 255) / 256, 256>>>(Wg2, wth + OWG2, wtl + OWG2, FF, HH);
    k_wt<<<(HH * HG + 255) / 256, 256>>>(Wl1, wth + OWL1, wtl + OWL1, HH, HG);
    k_wt<<<(HH * HG + 255) / 256, 256>>>(Wr1, wth + OWR1, wtl + OWR1, HH, HG);
    k_wt<<<(HH * HG + 255) / 256, 256>>>(Wl2, wth + OWL2, wtl + OWL2, HH, HG);
    k_wt<<<(HH * HG + 255) / 256, 256>>>(Wr2, wth + OWR2, wtl + OWR2, HH, HG);
    k_wt<<<(HG * HG + 255) / 256, 256>>>(Wm1, wth + OWM1, wtl + OWM1, HG, HG);

    // --- build CSR for both graphs ---
    k_zero_int<<<gN, TB>>>(deg1, NN);
    k_zero_int<<<gN, TB>>>(deg2, NN);
    k_deg<<<gE, TB>>>(dst1, deg1);
    k_deg<<<gE, TB>>>(dst2, deg2);
    k_scan<<<1, 1024>>>(deg1, rp1, NN);
    k_scan<<<1, 1024>>>(deg2, rp2, NN);
    k_disinv<<<gN, TB>>>(deg1, dis1, inv1);
    k_disinv<<<gN, TB>>>(deg2, dis2, inv2);
    k_copy_int<<<gN, TB>>>(cur1, rp1, NN);
    k_copy_int<<<gN, TB>>>(cur2, rp2, NN);
    k_place<<<gE, TB>>>(src1, dst1, cur1, col1);
    k_place<<<gE, TB>>>(src2, dst2, cur2, col2);

    // --- MMA GEMM setup ---
    cudaFuncSetAttribute(k_mma, cudaFuncAttributeMaxDynamicSharedMemorySize, SMEM_MMA);
    const int GY = (NN + 127) / 128;  // 782
    dim3 g256(HH / 128, GY);          // (2, 782)
    dim3 g128(HG / 128, GY);          // (1, 782)

    // --- GCN layer: XW = x @ Wg ---
    k_mma<<<g256, 256, SMEM_MMA>>>(x,  wth + OWG1, wtl + OWG1, FF,
                                   nullptr, nullptr, nullptr, 0,
                                   XW1, HH, nullptr, 0);
    k_mma<<<g256, 256, SMEM_MMA>>>(x1, wth + OWG2, wtl + OWG2, FF,
                                   nullptr, nullptr, nullptr, 0,
                                   XW2, HH, nullptr, 0);

    const int gW = NN / 8;
    k_gcn<<<gW, 256>>>(XW1, rp1, col1, dis1, bg1, 0);
    k_gcn<<<gW, 256>>>(XW2, rp2, col2, dis2, bg2, 1);

    // --- branch A: SAGE(graph1, X0) -> MLP ---
    k_sage<<<gW, 256>>>(X0, rp1, col1, inv1);
    k_mma<<<g128, 256, SMEM_MMA>>>(MEAN, wth + OWL1, wtl + OWL1, HH,
                                   X0,   wth + OWR1, wtl + OWR1, HH,
                                   A1, HG, bl1, 1);
    k_mma<<<g128, 256, SMEM_MMA>>>(A1, wth + OWM1, wtl + OWM1, HG,
                                   nullptr, nullptr, nullptr, 0,
                                   MEAN, HG, bm1, 0);
    k_lndot<<<gW, 256>>>(MEAN, lnw, lnb, Wm2, bm2, 0);

    // --- branch B: SAGE(graph2, G1) -> MLP ---
    k_sage<<<gW, 256>>>(G1, rp2, col2, inv2);
    k_mma<<<g128, 256, SMEM_MMA>>>(MEAN, wth + OWL2, wtl + OWL2, HH,
                                   G1,   wth + OWR2, wtl + OWR2, HH,
                                   A1, HG, bl2, 1);
    k_mma<<<g128, 256, SMEM_MMA>>>(A1, wth + OWM1, wtl + OWM1, HG,
                                   nullptr, nullptr, nullptr, 0,
                                   MEAN, HG, bm1, 0);
    k_lndot<<<gW, 256>>>(MEAN, lnw, lnb, Wm2, bm2, NN / 8);

    k_final<<<1, 1024>>>((float*)d_out);
}

// round 4
// speedup vs baseline: 2.4466x; 1.3099x over previous
#include <cuda_runtime.h>
#include <cuda_bf16.h>
#include <cstdint>

#define NN 100000
#define EE 600000
#define FF 512
#define HH 256
#define HG 128   // H2

typedef __nv_bfloat16 bf16;
typedef __nv_bfloat162 bf162;

// ---------------- scratch (static __device__ — no allocations) ----------------
__device__ bf16 g_xb1[(size_t)NN * FF];
__device__ bf16 g_xb2[(size_t)NN * FF];
__device__ bf16 g_XW1[(size_t)NN * HH];
__device__ bf16 g_XW2[(size_t)NN * HH];
__device__ bf16 g_X0 [(size_t)NN * HH];
__device__ bf16 g_G1 [(size_t)NN * HH];
__device__ bf16 g_MEAN[(size_t)NN * HH];   // also reused as MLP hidden T [N,128]
__device__ bf16 g_A1 [(size_t)NN * HG];
__device__ float g_dis1[NN], g_dis2[NN], g_inv1[NN], g_inv2[NN];
__device__ int   g_deg1[NN], g_deg2[NN];
__device__ int   g_rp1[NN + 1], g_rp2[NN + 1];
__device__ int   g_cur1[NN + 1], g_cur2[NN + 1];
__device__ int   g_col1[EE], g_col2[EE];
__device__ float g_part[25000];

// pre-split, pre-transposed weights (bf16 hi/lo), layout WT[n*K + k]
#define OWG1 0
#define OWG2 131072
#define OWL1 262144
#define OWR1 294912
#define OWL2 327680
#define OWR2 360448
#define OWM1 393216
__device__ bf16 g_wth[409600];
__device__ bf16 g_wtl[409600];

// ---------------- conversion kernels ----------------
__global__ void k_f2b(const float* __restrict__ in, bf16* __restrict__ out, int n4) {
    int i = blockIdx.x * blockDim.x + threadIdx.x;
    if (i < n4) {
        float4 v = ((const float4*)in)[i];
        bf162 a = __float22bfloat162_rn(make_float2(v.x, v.y));
        bf162 b = __float22bfloat162_rn(make_float2(v.z, v.w));
        ((uint2*)out)[i] = make_uint2(*(uint32_t*)&a, *(uint32_t*)&b);
    }
}

__global__ void k_wt(const float* __restrict__ W, bf16* __restrict__ th,
                     bf16* __restrict__ tl, int K, int M) {
    int i = blockIdx.x * blockDim.x + threadIdx.x;
    if (i < K * M) {
        int k = i / M, n = i % M;
        float w = W[i];
        bf16 h = __float2bfloat16(w);
        th[(size_t)n * K + k] = h;
        tl[(size_t)n * K + k] = __float2bfloat16(w - __bfloat162float(h));
    }
}

// ---------------- MMA GEMM: C[NN,M] = A1@W1 (+ A2@W2) (+bias)(relu), bf16 out ----
// A bf16 (cp.async), W pre-split bf16 hi+lo.
// BM=128, BN=128, BK=32, 256 threads, double-buffered cp.async.
#define LDSB 80          // bytes per smem row (32 bf16 = 64B + 16B pad)
#define STG_T 10240      // 128 rows * 80B
#define OFF_A  0
#define OFF_BH 20480
#define OFF_BL 40960
#define SMEM_MMA 61440

__device__ __forceinline__ void cpa16(uint32_t dst, const void* src) {
    asm volatile("cp.async.ca.shared.global [%0], [%1], 16;"
                 :: "r"(dst), "l"(src));
}

__device__ __forceinline__ void mma_bf16(float* c, const uint32_t* a, const uint32_t* b) {
    asm volatile(
        "mma.sync.aligned.m16n8k16.row.col.f32.bf16.bf16.f32 "
        "{%0,%1,%2,%3}, {%4,%5,%6,%7}, {%8,%9}, {%0,%1,%2,%3};"
        : "+f"(c[0]), "+f"(c[1]), "+f"(c[2]), "+f"(c[3])
        : "r"(a[0]), "r"(a[1]), "r"(a[2]), "r"(a[3]), "r"(b[0]), "r"(b[1]));
}

__global__ void __launch_bounds__(256, 1)
k_mma(const bf16* __restrict__ A1p, const bf16* __restrict__ W1h,
      const bf16* __restrict__ W1l, int K1,
      const bf16* __restrict__ A2p, const bf16* __restrict__ W2h,
      const bf16* __restrict__ W2l, int K2,
      bf16* __restrict__ C, int M,
      const float* __restrict__ bias, int reluflag)
{
    extern __shared__ __align__(16) char smem[];
    const uint32_t sb = (uint32_t)__cvta_generic_to_shared(smem);
    const int tid = threadIdx.x;
    const int wid = tid >> 5, lane = tid & 31;
    const int warp_m = wid & 1, warp_n = wid >> 1;
    const int rowBase = blockIdx.y * 128;
    const int colBase = blockIdx.x * 128;

    const int n1 = K1 >> 5;
    const int n2 = A2p ? (K2 >> 5) : 0;
    const int total = n1 + n2;

    float acc[4][4][4];
#pragma unroll
    for (int i = 0; i < 4; i++)
#pragma unroll
        for (int j = 0; j < 4; j++)
#pragma unroll
            for (int q = 0; q < 4; q++) acc[i][j][q] = 0.0f;

    auto pick = [&](int it, const bf16*& A, const bf16*& Wh,
                    const bf16*& Wl, int& K, int& k0) {
        if (it < n1) { A = A1p; Wh = W1h; Wl = W1l; K = K1; k0 = it << 5; }
        else         { A = A2p; Wh = W2h; Wl = W2l; K = K2; k0 = (it - n1) << 5; }
    };

    auto issue = [&](int it, int stage) {
        const bf16 *A, *Wh, *Wl; int K, k0;
        pick(it, A, Wh, Wl, K, k0);
        // A tile: 128 rows x 32 bf16 (64B) -> 512 x 16B
#pragma unroll
        for (int i = 0; i < 2; i++) {
            int idx = tid + i * 256;
            int r = idx >> 2, part = idx & 3;
            int gr = rowBase + r;
            uint32_t d = sb + OFF_A + stage * STG_T + r * LDSB + part * 16;
            if (gr < NN) cpa16(d, A + (size_t)gr * K + k0 + part * 8);
            else asm volatile("st.shared.v4.b32 [%0], {%1,%1,%1,%1};" :: "r"(d), "r"(0));
        }
        // B hi/lo tiles
#pragma unroll
        for (int i = 0; i < 2; i++) {
            int idx = tid + i * 256;
            int n = idx >> 2, part = idx & 3;
            int gn = colBase + n;
            uint32_t d = stage * STG_T + n * LDSB + part * 16;
            cpa16(sb + OFF_BH + d, Wh + (size_t)gn * K + k0 + part * 8);
            cpa16(sb + OFF_BL + d, Wl + (size_t)gn * K + k0 + part * 8);
        }
        asm volatile("cp.async.commit_group;");
    };

    auto compute = [&](int stage) {
#pragma unroll
        for (int ks = 0; ks < 2; ks++) {
            const int kk = ks * 16;
            uint32_t af[4][4];
#pragma unroll
            for (int mi = 0; mi < 4; mi++) {
                int row = warp_m * 64 + mi * 16 + (lane & 15);
                int kc = kk + ((lane >> 4) << 3);
                uint32_t ad = sb + OFF_A + stage * STG_T + row * LDSB + kc * 2;
                asm volatile("ldmatrix.sync.aligned.m8n8.x4.shared.b16 "
                             "{%0,%1,%2,%3}, [%4];"
                             : "=r"(af[mi][0]), "=r"(af[mi][1]),
                               "=r"(af[mi][2]), "=r"(af[mi][3]) : "r"(ad));
            }
            uint32_t bh[4][2], bl[4][2];
#pragma unroll
            for (int ni = 0; ni < 4; ni++) {
                int rn = warp_n * 32 + ni * 8 + (lane & 7);
                int kc = kk + ((lane >> 3) & 1) * 8;
                uint32_t off = stage * STG_T + rn * LDSB + kc * 2;
                asm volatile("ldmatrix.sync.aligned.m8n8.x2.shared.b16 {%0,%1}, [%2];"
                             : "=r"(bh[ni][0]), "=r"(bh[ni][1])
                             : "r"(sb + OFF_BH + off));
                asm volatile("ldmatrix.sync.aligned.m8n8.x2.shared.b16 {%0,%1}, [%2];"
                             : "=r"(bl[ni][0]), "=r"(bl[ni][1])
                             : "r"(sb + OFF_BL + off));
            }
#pragma unroll
            for (int mi = 0; mi < 4; mi++)
#pragma unroll
                for (int ni = 0; ni < 4; ni++) {
                    mma_bf16(acc[mi][ni], af[mi], bh[ni]);
                    mma_bf16(acc[mi][ni], af[mi], bl[ni]);
                }
        }
    };

    issue(0, 0);
    asm volatile("cp.async.wait_group 0;");
    __syncthreads();

    int stage = 0;
    for (int it = 0; it < total; ++it) {
        if (it + 1 < total) issue(it + 1, stage ^ 1);
        compute(stage);
        if (it + 1 < total) asm volatile("cp.async.wait_group 0;");
        __syncthreads();
        stage ^= 1;
    }

    // epilogue: bf16 out
    const int g = lane >> 2, tg = lane & 3;
#pragma unroll
    for (int mi = 0; mi < 4; mi++) {
#pragma unroll
        for (int ni = 0; ni < 4; ni++) {
            int col = colBase + warp_n * 32 + ni * 8 + tg * 2;
            float b0 = 0.f, b1 = 0.f;
            if (bias) { b0 = bias[col]; b1 = bias[col + 1]; }
            int row = rowBase + warp_m * 64 + mi * 16 + g;
            if (row < NN) {
                float vx = acc[mi][ni][0] + b0, vy = acc[mi][ni][1] + b1;
                if (reluflag) { vx = fmaxf(vx, 0.f); vy = fmaxf(vy, 0.f); }
                bf162 h = __float22bfloat162_rn(make_float2(vx, vy));
                *(bf162*)(C + (size_t)row * M + col) = h;
            }
            if (row + 8 < NN) {
                float vx = acc[mi][ni][2] + b0, vy = acc[mi][ni][3] + b1;
                if (reluflag) { vx = fmaxf(vx, 0.f); vy = fmaxf(vy, 0.f); }
                bf162 h = __float22bfloat162_rn(make_float2(vx, vy));
                *(bf162*)(C + (size_t)(row + 8) * M + col) = h;
            }
        }
    }
}

// ---------------- small utility kernels ----------------
__global__ void k_zero_int(int* p, int n) {
    int i = blockIdx.x * blockDim.x + threadIdx.x;
    if (i < n) p[i] = 0;
}

__global__ void k_copy_int(int* dst, const int* src, int n) {
    int i = blockIdx.x * blockDim.x + threadIdx.x;
    if (i < n) dst[i] = src[i];
}

__global__ void k_deg(const int* __restrict__ dst, int* __restrict__ deg) {
    int e = blockIdx.x * blockDim.x + threadIdx.x;
    if (e < EE) atomicAdd(&deg[dst[e]], 1);
}

__global__ void k_scan(const int* __restrict__ deg, int* __restrict__ rp, int n) {
    __shared__ int s[1024];
    int t = threadIdx.x;
    int chunk = (n + 1023) >> 10;
    int b = t * chunk;
    int e = b + chunk; if (e > n) e = n;
    int local = 0;
    for (int i = b; i < e && i < n; i++) local += deg[i];
    s[t] = local;
    __syncthreads();
    for (int off = 1; off < 1024; off <<= 1) {
        int v = (t >= off) ? s[t - off] : 0;
        __syncthreads();
        s[t] += v;
        __syncthreads();
    }
    int run = (t == 0) ? 0 : s[t - 1];
    for (int i = b; i < e && i < n; i++) { rp[i] = run; run += deg[i]; }
    if (t == 1023) rp[n] = s[1023];
}

__global__ void k_disinv(const int* __restrict__ deg, float* __restrict__ dis,
                         float* __restrict__ inv) {
    int i = blockIdx.x * blockDim.x + threadIdx.x;
    if (i < NN) {
        float d = (float)deg[i];
        dis[i] = rsqrtf(d + 1.0f);
        inv[i] = 1.0f / fmaxf(d, 1.0f);
    }
}

__global__ void k_place(const int* __restrict__ src, const int* __restrict__ dst,
                        int* __restrict__ cur, int* __restrict__ col) {
    int e = blockIdx.x * blockDim.x + threadIdx.x;
    if (e < EE) {
        int d = dst[e];
        int p = atomicAdd(&cur[d], 1);
        col[p] = src[e];
    }
}

// ---------------- helpers for bf16 gather ----------------
__device__ __forceinline__ void unp8(uint4 v, float* f) {
    float2 a = __bfloat1622float2(*(bf162*)&v.x);
    float2 b = __bfloat1622float2(*(bf162*)&v.y);
    float2 c = __bfloat1622float2(*(bf162*)&v.z);
    float2 d = __bfloat1622float2(*(bf162*)&v.w);
    f[0] = a.x; f[1] = a.y; f[2] = b.x; f[3] = b.y;
    f[4] = c.x; f[5] = c.y; f[6] = d.x; f[7] = d.y;
}

__device__ __forceinline__ uint4 pk8(const float* f) {
    bf162 a = __float22bfloat162_rn(make_float2(f[0], f[1]));
    bf162 b = __float22bfloat162_rn(make_float2(f[2], f[3]));
    bf162 c = __float22bfloat162_rn(make_float2(f[4], f[5]));
    bf162 d = __float22bfloat162_rn(make_float2(f[6], f[7]));
    return make_uint4(*(uint32_t*)&a, *(uint32_t*)&b, *(uint32_t*)&c, *(uint32_t*)&d);
}

// ---------------- GCN aggregation (warp per node, gather over CSR, bf16) ----------
__global__ void k_gcn(const bf16* __restrict__ xw, const int* __restrict__ rp,
                      const int* __restrict__ col, const float* __restrict__ dis,
                      const float* __restrict__ bias, int mode) {
    int node = blockIdx.x * 8 + (threadIdx.x >> 5);
    int lane = threadIdx.x & 31;
    if (node >= NN) return;

    const uint4* xw4 = (const uint4*)xw;   // 32 uint4 per 256-col row
    float acc[8] = {0, 0, 0, 0, 0, 0, 0, 0};
    int e0 = rp[node], e1 = rp[node + 1];
    for (int e = e0; e < e1; e++) {
        int s = col[e];
        float ds = dis[s];
        float f[8];
        unp8(xw4[(size_t)s * 32 + lane], f);
#pragma unroll
        for (int u = 0; u < 8; u++) acc[u] += f[u] * ds;
    }
    float di = dis[node];
    float dii = di * di;
    float sf[8];
    unp8(xw4[(size_t)node * 32 + lane], sf);
    const float4* b4 = (const float4*)bias;
    float4 bb0 = b4[2 * lane], bb1 = b4[2 * lane + 1];
    float bb[8] = {bb0.x, bb0.y, bb0.z, bb0.w, bb1.x, bb1.y, bb1.z, bb1.w};

    float v[8], r[8];
#pragma unroll
    for (int u = 0; u < 8; u++) {
        v[u] = acc[u] * di + sf[u] * dii + bb[u];
        r[u] = fmaxf(v[u], 0.f);
    }

    size_t o = (size_t)node * 32 + lane;
    uint4* X04 = (uint4*)g_X0;
    if (mode == 0) {
        X04[o] = pk8(r);
    } else {
        float xs[8];
        unp8(X04[o], xs);
#pragma unroll
        for (int u = 0; u < 8; u++) xs[u] += r[u];
        X04[o] = pk8(xs);
        float gg[8];
#pragma unroll
        for (int u = 0; u < 8; u++) gg[u] = r[u] + v[u];
        ((uint4*)g_G1)[o] = pk8(gg);
    }
}

// ---------------- SAGE mean aggregation (warp per node, bf16) -> g_MEAN ----------
__global__ void k_sage(const bf16* __restrict__ feat, const int* __restrict__ rp,
                       const int* __restrict__ col, const float* __restrict__ inv) {
    int node = blockIdx.x * 8 + (threadIdx.x >> 5);
    int lane = threadIdx.x & 31;
    if (node >= NN) return;

    const uint4* f4 = (const uint4*)feat;
    float acc[8] = {0, 0, 0, 0, 0, 0, 0, 0};
    int e0 = rp[node], e1 = rp[node + 1];
    for (int e = e0; e < e1; e++) {
        int s = col[e];
        float f[8];
        unp8(f4[(size_t)s * 32 + lane], f);
#pragma unroll
        for (int u = 0; u < 8; u++) acc[u] += f[u];
    }
    float ic = inv[node];
#pragma unroll
    for (int u = 0; u < 8; u++) acc[u] *= ic;
    ((uint4*)g_MEAN)[(size_t)node * 32 + lane] = pk8(acc);
}

// ---------------- LayerNorm + final dot, warp per row (bf16 T) ----------------
__device__ __forceinline__ float warp_sum(float v) {
#pragma unroll
    for (int o = 16; o; o >>= 1) v += __shfl_xor_sync(0xffffffffu, v, o);
    return v;
}

__global__ void k_lndot(const bf16* __restrict__ T, const float* __restrict__ lnw,
                        const float* __restrict__ lnb, const float* __restrict__ wm2,
                        const float* __restrict__ bm2, int poff) {
    __shared__ float ws[8];
    int wid = threadIdx.x >> 5, lane = threadIdx.x & 31;
    int row = blockIdx.x * 8 + wid;
    float y = 0.0f;
    if (row < NN) {
        uint2 tv = ((const uint2*)T)[(size_t)row * 32 + lane];
        float2 t01 = __bfloat1622float2(*(bf162*)&tv.x);
        float2 t23 = __bfloat1622float2(*(bf162*)&tv.y);
        float sum = t01.x + t01.y + t23.x + t23.y;
        float sq = t01.x * t01.x + t01.y * t01.y + t23.x * t23.x + t23.y * t23.y;
        sum = warp_sum(sum);
        sq = warp_sum(sq);
        float mu = sum * (1.0f / 128.0f);
        float var = sq * (1.0f / 128.0f) - mu * mu;
        float rs = rsqrtf(var + 1e-5f);
        float4 w = ((const float4*)lnw)[lane];
        float4 b = ((const float4*)lnb)[lane];
        float4 m = ((const float4*)wm2)[lane];
        float p = ((t01.x - mu) * rs * w.x + b.x) * m.x
                + ((t01.y - mu) * rs * w.y + b.y) * m.y
                + ((t23.x - mu) * rs * w.z + b.z) * m.z
                + ((t23.y - mu) * rs * w.w + b.w) * m.w;
        p = warp_sum(p);
        y = p + bm2[0];
    }
    if (lane == 0) ws[wid] = y;
    __syncthreads();
    if (threadIdx.x == 0) {
        float s = 0;
#pragma unroll
        for (int i = 0; i < 8; i++) s += ws[i];
        g_part[poff + blockIdx.x] = s;
    }
}

__global__ void k_final(float* out) {
    __shared__ float s[1024];
    int t = threadIdx.x;
    float v = 0;
    for (int i = t; i < 25000; i += 1024) v += g_part[i];
    s[t] = v;
    __syncthreads();
    for (int off = 512; off; off >>= 1) {
        if (t < off) s[t] += s[t + off];
        __syncthreads();
    }
    if (t == 0) out[0] = s[0] * (1.0f / (2.0f * (float)NN));
}

// ---------------- host ----------------
static void* symaddr(const void* s) {
    void* p = nullptr;
    cudaGetSymbolAddress(&p, s);
    return p;
}

extern "C" void kernel_launch(void* const* d_in, const int* in_sizes, int n_in,
                              void* d_out, int out_size) {
    const float* x   = (const float*)d_in[0];
    const float* x1  = (const float*)d_in[1];
    const int*   ei  = (const int*)d_in[2];
    const int*   ei1 = (const int*)d_in[3];
    const float* Wg1 = (const float*)d_in[4];
    const float* bg1 = (const float*)d_in[5];
    const float* Wg2 = (const float*)d_in[6];
    const float* bg2 = (const float*)d_in[7];
    const float* Wl1 = (const float*)d_in[8];
    const float* bl1 = (const float*)d_in[9];
    const float* Wr1 = (const float*)d_in[10];
    const float* Wl2 = (const float*)d_in[11];
    const float* bl2 = (const float*)d_in[12];
    const float* Wr2 = (const float*)d_in[13];
    const float* Wm1 = (const float*)d_in[14];
    const float* bm1 = (const float*)d_in[15];
    const float* lnw = (const float*)d_in[16];
    const float* lnb = (const float*)d_in[17];
    const float* Wm2 = (const float*)d_in[18];
    const float* bm2 = (const float*)d_in[19];

    const int* src1 = ei;
    const int* dst1 = ei + EE;
    const int* src2 = ei1;
    const int* dst2 = ei1 + EE;

    bf16* xb1  = (bf16*)symaddr(g_xb1);
    bf16* xb2  = (bf16*)symaddr(g_xb2);
    bf16* XW1  = (bf16*)symaddr(g_XW1);
    bf16* XW2  = (bf16*)symaddr(g_XW2);
    bf16* X0   = (bf16*)symaddr(g_X0);
    bf16* G1   = (bf16*)symaddr(g_G1);
    bf16* MEAN = (bf16*)symaddr(g_MEAN);
    bf16* A1   = (bf16*)symaddr(g_A1);
    float* dis1 = (float*)symaddr(g_dis1);
    float* dis2 = (float*)symaddr(g_dis2);
    float* inv1 = (float*)symaddr(g_inv1);
    float* inv2 = (float*)symaddr(g_inv2);
    int* deg1 = (int*)symaddr(g_deg1);
    int* deg2 = (int*)symaddr(g_deg2);
    int* rp1  = (int*)symaddr(g_rp1);
    int* rp2  = (int*)symaddr(g_rp2);
    int* cur1 = (int*)symaddr(g_cur1);
    int* cur2 = (int*)symaddr(g_cur2);
    int* col1 = (int*)symaddr(g_col1);
    int* col2 = (int*)symaddr(g_col2);
    bf16* wth = (bf16*)symaddr(g_wth);
    bf16* wtl = (bf16*)symaddr(g_wtl);

    const int TB = 256;
    const int gN = (NN + TB - 1) / TB;
    const int gE = (EE + TB - 1) / TB;

    // --- input conversion + weight split/transpose ---
    const int n4 = NN * FF / 4;
    k_f2b<<<(n4 + 255) / 256, 256>>>(x,  xb1, n4);
    k_f2b<<<(n4 + 255) / 256, 256>>>(x1, xb2, n4);
    k_wt<<<(FF * HH + 255) / 256, 256>>>(Wg1, wth + OWG1, wtl + OWG1, FF, HH);
    k_wt<<<(FF * HH + 255) / 256, 256>>>(Wg2, wth + OWG2, wtl + OWG2, FF, HH);
    k_wt<<<(HH * HG + 255) / 256, 256>>>(Wl1, wth + OWL1, wtl + OWL1, HH, HG);
    k_wt<<<(HH * HG + 255) / 256, 256>>>(Wr1, wth + OWR1, wtl + OWR1, HH, HG);
    k_wt<<<(HH * HG + 255) / 256, 256>>>(Wl2, wth + OWL2, wtl + OWL2, HH, HG);
    k_wt<<<(HH * HG + 255) / 256, 256>>>(Wr2, wth + OWR2, wtl + OWR2, HH, HG);
    k_wt<<<(HG * HG + 255) / 256, 256>>>(Wm1, wth + OWM1, wtl + OWM1, HG, HG);

    // --- build CSR for both graphs ---
    k_zero_int<<<gN, TB>>>(deg1, NN);
    k_zero_int<<<gN, TB>>>(deg2, NN);
    k_deg<<<gE, TB>>>(dst1, deg1);
    k_deg<<<gE, TB>>>(dst2, deg2);
    k_scan<<<1, 1024>>>(deg1, rp1, NN);
    k_scan<<<1, 1024>>>(deg2, rp2, NN);
    k_disinv<<<gN, TB>>>(deg1, dis1, inv1);
    k_disinv<<<gN, TB>>>(deg2, dis2, inv2);
    k_copy_int<<<gN, TB>>>(cur1, rp1, NN);
    k_copy_int<<<gN, TB>>>(cur2, rp2, NN);
    k_place<<<gE, TB>>>(src1, dst1, cur1, col1);
    k_place<<<gE, TB>>>(src2, dst2, cur2, col2);

    // --- MMA GEMM setup ---
    cudaFuncSetAttribute(k_mma, cudaFuncAttributeMaxDynamicSharedMemorySize, SMEM_MMA);
    const int GY = (NN + 127) / 128;  // 782
    dim3 g256(HH / 128, GY);
    dim3 g128(HG / 128, GY);

    // --- GCN layer: XW = x @ Wg ---
    k_mma<<<g256, 256, SMEM_MMA>>>(xb1, wth + OWG1, wtl + OWG1, FF,
                                   nullptr, nullptr, nullptr, 0,
                                   XW1, HH, nullptr, 0);
    k_mma<<<g256, 256, SMEM_MMA>>>(xb2, wth + OWG2, wtl + OWG2, FF,
                                   nullptr, nullptr, nullptr, 0,
                                   XW2, HH, nullptr, 0);

    const int gW = NN / 8;
    k_gcn<<<gW, 256>>>(XW1, rp1, col1, dis1, bg1, 0);
    k_gcn<<<gW, 256>>>(XW2, rp2, col2, dis2, bg2, 1);

    // --- branch A: SAGE(graph1, X0) -> MLP ---
    k_sage<<<gW, 256>>>(X0, rp1, col1, inv1);
    k_mma<<<g128, 256, SMEM_MMA>>>(MEAN, wth + OWL1, wtl + OWL1, HH,
                                   X0,   wth + OWR1, wtl + OWR1, HH,
                                   A1, HG, bl1, 1);
    k_mma<<<g128, 256, SMEM_MMA>>>(A1, wth + OWM1, wtl + OWM1, HG,
                                   nullptr, nullptr, nullptr, 0,
                                   MEAN, HG, bm1, 0);
    k_lndot<<<gW, 256>>>(MEAN, lnw, lnb, Wm2, bm2, 0);

    // --- branch B: SAGE(graph2, G1) -> MLP ---
    k_sage<<<gW, 256>>>(G1, rp2, col2, inv2);
    k_mma<<<g128, 256, SMEM_MMA>>>(MEAN, wth + OWL2, wtl + OWL2, HH,
                                   G1,   wth + OWR2, wtl + OWR2, HH,
                                   A1, HG, bl2, 1);
    k_mma<<<g128, 256, SMEM_MMA>>>(A1, wth + OWM1, wtl + OWM1, HG,
                                   nullptr, nullptr, nullptr, 0,
                                   MEAN, HG, bm1, 0);
    k_lndot<<<gW, 256>>>(MEAN, lnw, lnb, Wm2, bm2, NN / 8);

    k_final<<<1, 1024>>>((float*)d_out);
}

// round 5
// speedup vs baseline: 3.3174x; 1.3559x over previous
#include <cuda_runtime.h>
#include <cuda_fp16.h>
#include <cstdint>

#define NN 100000
#define EE 600000
#define FF 512
#define HH 256
#define HG 128   // H2

typedef __half fp16;
typedef __half2 fp162;

// ---------------- scratch (static __device__ — no allocations) ----------------
__device__ fp16 g_xb1[(size_t)NN * FF];
__device__ fp16 g_xb2[(size_t)NN * FF];
__device__ fp16 g_XW1[(size_t)NN * HH];
__device__ fp16 g_XW2[(size_t)NN * HH];
__device__ fp16 g_X0 [(size_t)NN * HH];
__device__ fp16 g_G1 [(size_t)NN * HH];
__device__ fp16 g_MEAN[(size_t)NN * HH];   // also reused as MLP hidden T [N,128]
__device__ fp16 g_A1 [(size_t)NN * HG];
__device__ float g_dis1[NN], g_dis2[NN], g_inv1[NN], g_inv2[NN];
__device__ int   g_deg1[NN], g_deg2[NN];
__device__ int   g_rp1[NN + 1], g_rp2[NN + 1];
__device__ int   g_cur1[NN + 1], g_cur2[NN + 1];
__device__ int   g_col1[EE], g_col2[EE];
__device__ float g_part[25000];

// pre-transposed fp16 weights, layout WT[n*K + k]
#define OWG1 0
#define OWG2 131072
#define OWL1 262144
#define OWR1 294912
#define OWL2 327680
#define OWR2 360448
#define OWM1 393216
__device__ fp16 g_wt[409600];

// ---------------- conversion kernels ----------------
__global__ void k_f2h(const float* __restrict__ in, fp16* __restrict__ out, int n4) {
    int i = blockIdx.x * blockDim.x + threadIdx.x;
    if (i < n4) {
        float4 v = ((const float4*)in)[i];
        fp162 a = __float22half2_rn(make_float2(v.x, v.y));
        fp162 b = __float22half2_rn(make_float2(v.z, v.w));
        ((uint2*)out)[i] = make_uint2(*(uint32_t*)&a, *(uint32_t*)&b);
    }
}

__global__ void k_wt(const float* __restrict__ W, fp16* __restrict__ th, int K, int M) {
    int i = blockIdx.x * blockDim.x + threadIdx.x;
    if (i < K * M) {
        int k = i / M, n = i % M;
        th[(size_t)n * K + k] = __float2half(W[i]);
    }
}

// ---------------- MMA GEMM: C[NN,M] = A1@W1 (+ A2@W2) (+bias)(relu), fp16 -------
// BM=128, BN=128, BK=32, 256 threads, double-buffered cp.async.
#define LDSB 80          // bytes per smem row (32 fp16 = 64B + 16B pad)
#define STG_T 10240      // 128 rows * 80B
#define OFF_A  0
#define OFF_B  20480
#define SMEM_MMA 40960

__device__ __forceinline__ void cpa16(uint32_t dst, const void* src) {
    asm volatile("cp.async.ca.shared.global [%0], [%1], 16;"
                 :: "r"(dst), "l"(src));
}

__device__ __forceinline__ void mma_fp16(float* c, const uint32_t* a, const uint32_t* b) {
    asm volatile(
        "mma.sync.aligned.m16n8k16.row.col.f32.f16.f16.f32 "
        "{%0,%1,%2,%3}, {%4,%5,%6,%7}, {%8,%9}, {%0,%1,%2,%3};"
        : "+f"(c[0]), "+f"(c[1]), "+f"(c[2]), "+f"(c[3])
        : "r"(a[0]), "r"(a[1]), "r"(a[2]), "r"(a[3]), "r"(b[0]), "r"(b[1]));
}

__global__ void __launch_bounds__(256, 2)
k_mma(const fp16* __restrict__ A1p, const fp16* __restrict__ W1, int K1,
      const fp16* __restrict__ A2p, const fp16* __restrict__ W2, int K2,
      fp16* __restrict__ C, int M,
      const float* __restrict__ bias, int reluflag)
{
    extern __shared__ __align__(16) char smem[];
    const uint32_t sb = (uint32_t)__cvta_generic_to_shared(smem);
    const int tid = threadIdx.x;
    const int wid = tid >> 5, lane = tid & 31;
    const int warp_m = wid & 1, warp_n = wid >> 1;
    const int rowBase = blockIdx.y * 128;
    const int colBase = blockIdx.x * 128;

    const int n1 = K1 >> 5;
    const int n2 = A2p ? (K2 >> 5) : 0;
    const int total = n1 + n2;

    float acc[4][4][4];
#pragma unroll
    for (int i = 0; i < 4; i++)
#pragma unroll
        for (int j = 0; j < 4; j++)
#pragma unroll
            for (int q = 0; q < 4; q++) acc[i][j][q] = 0.0f;

    auto pick = [&](int it, const fp16*& A, const fp16*& W, int& K, int& k0) {
        if (it < n1) { A = A1p; W = W1; K = K1; k0 = it << 5; }
        else         { A = A2p; W = W2; K = K2; k0 = (it - n1) << 5; }
    };

    auto issue = [&](int it, int stage) {
        const fp16 *A, *W; int K, k0;
        pick(it, A, W, K, k0);
#pragma unroll
        for (int i = 0; i < 2; i++) {
            int idx = tid + i * 256;
            int r = idx >> 2, part = idx & 3;
            int gr = rowBase + r;
            uint32_t d = sb + OFF_A + stage * STG_T + r * LDSB + part * 16;
            if (gr < NN) cpa16(d, A + (size_t)gr * K + k0 + part * 8);
            else asm volatile("st.shared.v4.b32 [%0], {%1,%1,%1,%1};" :: "r"(d), "r"(0));
        }
#pragma unroll
        for (int i = 0; i < 2; i++) {
            int idx = tid + i * 256;
            int n = idx >> 2, part = idx & 3;
            int gn = colBase + n;
            uint32_t d = sb + OFF_B + stage * STG_T + n * LDSB + part * 16;
            cpa16(d, W + (size_t)gn * K + k0 + part * 8);
        }
        asm volatile("cp.async.commit_group;");
    };

    auto compute = [&](int stage) {
#pragma unroll
        for (int ks = 0; ks < 2; ks++) {
            const int kk = ks * 16;
            uint32_t af[4][4];
#pragma unroll
            for (int mi = 0; mi < 4; mi++) {
                int row = warp_m * 64 + mi * 16 + (lane & 15);
                int kc = kk + ((lane >> 4) << 3);
                uint32_t ad = sb + OFF_A + stage * STG_T + row * LDSB + kc * 2;
                asm volatile("ldmatrix.sync.aligned.m8n8.x4.shared.b16 "
                             "{%0,%1,%2,%3}, [%4];"
                             : "=r"(af[mi][0]), "=r"(af[mi][1]),
                               "=r"(af[mi][2]), "=r"(af[mi][3]) : "r"(ad));
            }
            uint32_t bh[4][2];
#pragma unroll
            for (int ni = 0; ni < 4; ni++) {
                int rn = warp_n * 32 + ni * 8 + (lane & 7);
                int kc = kk + ((lane >> 3) & 1) * 8;
                uint32_t off = sb + OFF_B + stage * STG_T + rn * LDSB + kc * 2;
                asm volatile("ldmatrix.sync.aligned.m8n8.x2.shared.b16 {%0,%1}, [%2];"
                             : "=r"(bh[ni][0]), "=r"(bh[ni][1]) : "r"(off));
            }
#pragma unroll
            for (int mi = 0; mi < 4; mi++)
#pragma unroll
                for (int ni = 0; ni < 4; ni++)
                    mma_fp16(acc[mi][ni], af[mi], bh[ni]);
        }
    };

    issue(0, 0);
    asm volatile("cp.async.wait_group 0;");
    __syncthreads();

    int stage = 0;
    for (int it = 0; it < total; ++it) {
        if (it + 1 < total) issue(it + 1, stage ^ 1);
        compute(stage);
        if (it + 1 < total) asm volatile("cp.async.wait_group 0;");
        __syncthreads();
        stage ^= 1;
    }

    // epilogue: fp16 out
    const int g = lane >> 2, tg = lane & 3;
#pragma unroll
    for (int mi = 0; mi < 4; mi++) {
#pragma unroll
        for (int ni = 0; ni < 4; ni++) {
            int col = colBase + warp_n * 32 + ni * 8 + tg * 2;
            float b0 = 0.f, b1 = 0.f;
            if (bias) { b0 = bias[col]; b1 = bias[col + 1]; }
            int row = rowBase + warp_m * 64 + mi * 16 + g;
            if (row < NN) {
                float vx = acc[mi][ni][0] + b0, vy = acc[mi][ni][1] + b1;
                if (reluflag) { vx = fmaxf(vx, 0.f); vy = fmaxf(vy, 0.f); }
                fp162 h = __float22half2_rn(make_float2(vx, vy));
                *(fp162*)(C + (size_t)row * M + col) = h;
            }
            if (row + 8 < NN) {
                float vx = acc[mi][ni][2] + b0, vy = acc[mi][ni][3] + b1;
                if (reluflag) { vx = fmaxf(vx, 0.f); vy = fmaxf(vy, 0.f); }
                fp162 h = __float22half2_rn(make_float2(vx, vy));
                *(fp162*)(C + (size_t)(row + 8) * M + col) = h;
            }
        }
    }
}

// ---------------- small utility kernels ----------------
__global__ void k_zero_int(int* p, int n) {
    int i = blockIdx.x * blockDim.x + threadIdx.x;
    if (i < n) p[i] = 0;
}

__global__ void k_copy_int(int* dst, const int* src, int n) {
    int i = blockIdx.x * blockDim.x + threadIdx.x;
    if (i < n) dst[i] = src[i];
}

__global__ void k_deg(const int* __restrict__ dst, int* __restrict__ deg) {
    int e = blockIdx.x * blockDim.x + threadIdx.x;
    if (e < EE) atomicAdd(&deg[dst[e]], 1);
}

__global__ void k_scan(const int* __restrict__ deg, int* __restrict__ rp, int n) {
    __shared__ int s[1024];
    int t = threadIdx.x;
    int chunk = (n + 1023) >> 10;
    int b = t * chunk;
    int e = b + chunk; if (e > n) e = n;
    int local = 0;
    for (int i = b; i < e && i < n; i++) local += deg[i];
    s[t] = local;
    __syncthreads();
    for (int off = 1; off < 1024; off <<= 1) {
        int v = (t >= off) ? s[t - off] : 0;
        __syncthreads();
        s[t] += v;
        __syncthreads();
    }
    int run = (t == 0) ? 0 : s[t - 1];
    for (int i = b; i < e && i < n; i++) { rp[i] = run; run += deg[i]; }
    if (t == 1023) rp[n] = s[1023];
}

__global__ void k_disinv(const int* __restrict__ deg, float* __restrict__ dis,
                         float* __restrict__ inv) {
    int i = blockIdx.x * blockDim.x + threadIdx.x;
    if (i < NN) {
        float d = (float)deg[i];
        dis[i] = rsqrtf(d + 1.0f);
        inv[i] = 1.0f / fmaxf(d, 1.0f);
    }
}

__global__ void k_place(const int* __restrict__ src, const int* __restrict__ dst,
                        int* __restrict__ cur, int* __restrict__ col) {
    int e = blockIdx.x * blockDim.x + threadIdx.x;
    if (e < EE) {
        int d = dst[e];
        int p = atomicAdd(&cur[d], 1);
        col[p] = src[e];
    }
}

// ---------------- helpers for fp16 gather ----------------
__device__ __forceinline__ void unp8(uint4 v, float* f) {
    float2 a = __half22float2(*(fp162*)&v.x);
    float2 b = __half22float2(*(fp162*)&v.y);
    float2 c = __half22float2(*(fp162*)&v.z);
    float2 d = __half22float2(*(fp162*)&v.w);
    f[0] = a.x; f[1] = a.y; f[2] = b.x; f[3] = b.y;
    f[4] = c.x; f[5] = c.y; f[6] = d.x; f[7] = d.y;
}

__device__ __forceinline__ uint4 pk8(const float* f) {
    fp162 a = __float22half2_rn(make_float2(f[0], f[1]));
    fp162 b = __float22half2_rn(make_float2(f[2], f[3]));
    fp162 c = __float22half2_rn(make_float2(f[4], f[5]));
    fp162 d = __float22half2_rn(make_float2(f[6], f[7]));
    return make_uint4(*(uint32_t*)&a, *(uint32_t*)&b, *(uint32_t*)&c, *(uint32_t*)&d);
}

// ---------------- GCN aggregation (warp per node, gather over CSR, fp16) ----------
__global__ void k_gcn(const fp16* __restrict__ xw, const int* __restrict__ rp,
                      const int* __restrict__ col, const float* __restrict__ dis,
                      const float* __restrict__ bias, int mode) {
    int node = blockIdx.x * 8 + (threadIdx.x >> 5);
    int lane = threadIdx.x & 31;
    if (node >= NN) return;

    const uint4* xw4 = (const uint4*)xw;   // 32 uint4 per 256-col row
    float acc[8] = {0, 0, 0, 0, 0, 0, 0, 0};
    int e0 = rp[node], e1 = rp[node + 1];
    for (int e = e0; e < e1; e++) {
        int s = col[e];
        float ds = dis[s];
        float f[8];
        unp8(xw4[(size_t)s * 32 + lane], f);
#pragma unroll
        for (int u = 0; u < 8; u++) acc[u] += f[u] * ds;
    }
    float di = dis[node];
    float dii = di * di;
    float sf[8];
    unp8(xw4[(size_t)node * 32 + lane], sf);
    const float4* b4 = (const float4*)bias;
    float4 bb0 = b4[2 * lane], bb1 = b4[2 * lane + 1];
    float bb[8] = {bb0.x, bb0.y, bb0.z, bb0.w, bb1.x, bb1.y, bb1.z, bb1.w};

    float v[8], r[8];
#pragma unroll
    for (int u = 0; u < 8; u++) {
        v[u] = acc[u] * di + sf[u] * dii + bb[u];
        r[u] = fmaxf(v[u], 0.f);
    }

    size_t o = (size_t)node * 32 + lane;
    uint4* X04 = (uint4*)g_X0;
    if (mode == 0) {
        X04[o] = pk8(r);
    } else {
        float xs[8];
        unp8(X04[o], xs);
#pragma unroll
        for (int u = 0; u < 8; u++) xs[u] += r[u];
        X04[o] = pk8(xs);
        float gg[8];
#pragma unroll
        for (int u = 0; u < 8; u++) gg[u] = r[u] + v[u];
        ((uint4*)g_G1)[o] = pk8(gg);
    }
}

// ---------------- SAGE mean aggregation (warp per node, fp16) -> g_MEAN ----------
__global__ void k_sage(const fp16* __restrict__ feat, const int* __restrict__ rp,
                       const int* __restrict__ col, const float* __restrict__ inv) {
    int node = blockIdx.x * 8 + (threadIdx.x >> 5);
    int lane = threadIdx.x & 31;
    if (node >= NN) return;

    const uint4* f4 = (const uint4*)feat;
    float acc[8] = {0, 0, 0, 0, 0, 0, 0, 0};
    int e0 = rp[node], e1 = rp[node + 1];
    for (int e = e0; e < e1; e++) {
        int s = col[e];
        float f[8];
        unp8(f4[(size_t)s * 32 + lane], f);
#pragma unroll
        for (int u = 0; u < 8; u++) acc[u] += f[u];
    }
    float ic = inv[node];
#pragma unroll
    for (int u = 0; u < 8; u++) acc[u] *= ic;
    ((uint4*)g_MEAN)[(size_t)node * 32 + lane] = pk8(acc);
}

// ---------------- LayerNorm + final dot, warp per row (fp16 T) ----------------
__device__ __forceinline__ float warp_sum(float v) {
#pragma unroll
    for (int o = 16; o; o >>= 1) v += __shfl_xor_sync(0xffffffffu, v, o);
    return v;
}

__global__ void k_lndot(const fp16* __restrict__ T, const float* __restrict__ lnw,
                        const float* __restrict__ lnb, const float* __restrict__ wm2,
                        const float* __restrict__ bm2, int poff) {
    __shared__ float ws[8];
    int wid = threadIdx.x >> 5, lane = threadIdx.x & 31;
    int row = blockIdx.x * 8 + wid;
    float y = 0.0f;
    if (row < NN) {
        uint2 tv = ((const uint2*)T)[(size_t)row * 32 + lane];
        float2 t01 = __half22float2(*(fp162*)&tv.x);
        float2 t23 = __half22float2(*(fp162*)&tv.y);
        float sum = t01.x + t01.y + t23.x + t23.y;
        float sq = t01.x * t01.x + t01.y * t01.y + t23.x * t23.x + t23.y * t23.y;
        sum = warp_sum(sum);
        sq = warp_sum(sq);
        float mu = sum * (1.0f / 128.0f);
        float var = sq * (1.0f / 128.0f) - mu * mu;
        float rs = rsqrtf(var + 1e-5f);
        float4 w = ((const float4*)lnw)[lane];
        float4 b = ((const float4*)lnb)[lane];
        float4 m = ((const float4*)wm2)[lane];
        float p = ((t01.x - mu) * rs * w.x + b.x) * m.x
                + ((t01.y - mu) * rs * w.y + b.y) * m.y
                + ((t23.x - mu) * rs * w.z + b.z) * m.z
                + ((t23.y - mu) * rs * w.w + b.w) * m.w;
        p = warp_sum(p);
        y = p + bm2[0];
    }
    if (lane == 0) ws[wid] = y;
    __syncthreads();
    if (threadIdx.x == 0) {
        float s = 0;
#pragma unroll
        for (int i = 0; i < 8; i++) s += ws[i];
        g_part[poff + blockIdx.x] = s;
    }
}

__global__ void k_final(float* out) {
    __shared__ float s[1024];
    int t = threadIdx.x;
    float v = 0;
    for (int i = t; i < 25000; i += 1024) v += g_part[i];
    s[t] = v;
    __syncthreads();
    for (int off = 512; off; off >>= 1) {
        if (t < off) s[t] += s[t + off];
        __syncthreads();
    }
    if (t == 0) out[0] = s[0] * (1.0f / (2.0f * (float)NN));
}

// ---------------- host ----------------
static void* symaddr(const void* s) {
    void* p = nullptr;
    cudaGetSymbolAddress(&p, s);
    return p;
}

extern "C" void kernel_launch(void* const* d_in, const int* in_sizes, int n_in,
                              void* d_out, int out_size) {
    const float* x   = (const float*)d_in[0];
    const float* x1  = (const float*)d_in[1];
    const int*   ei  = (const int*)d_in[2];
    const int*   ei1 = (const int*)d_in[3];
    const float* Wg1 = (const float*)d_in[4];
    const float* bg1 = (const float*)d_in[5];
    const float* Wg2 = (const float*)d_in[6];
    const float* bg2 = (const float*)d_in[7];
    const float* Wl1 = (const float*)d_in[8];
    const float* bl1 = (const float*)d_in[9];
    const float* Wr1 = (const float*)d_in[10];
    const float* Wl2 = (const float*)d_in[11];
    const float* bl2 = (const float*)d_in[12];
    const float* Wr2 = (const float*)d_in[13];
    const float* Wm1 = (const float*)d_in[14];
    const float* bm1 = (const float*)d_in[15];
    const float* lnw = (const float*)d_in[16];
    const float* lnb = (const float*)d_in[17];
    const float* Wm2 = (const float*)d_in[18];
    const float* bm2 = (const float*)d_in[19];

    const int* src1 = ei;
    const int* dst1 = ei + EE;
    const int* src2 = ei1;
    const int* dst2 = ei1 + EE;

    fp16* xb1  = (fp16*)symaddr(g_xb1);
    fp16* xb2  = (fp16*)symaddr(g_xb2);
    fp16* XW1  = (fp16*)symaddr(g_XW1);
    fp16* XW2  = (fp16*)symaddr(g_XW2);
    fp16* X0   = (fp16*)symaddr(g_X0);
    fp16* G1   = (fp16*)symaddr(g_G1);
    fp16* MEAN = (fp16*)symaddr(g_MEAN);
    fp16* A1   = (fp16*)symaddr(g_A1);
    float* dis1 = (float*)symaddr(g_dis1);
    float* dis2 = (float*)symaddr(g_dis2);
    float* inv1 = (float*)symaddr(g_inv1);
    float* inv2 = (float*)symaddr(g_inv2);
    int* deg1 = (int*)symaddr(g_deg1);
    int* deg2 = (int*)symaddr(g_deg2);
    int* rp1  = (int*)symaddr(g_rp1);
    int* rp2  = (int*)symaddr(g_rp2);
    int* cur1 = (int*)symaddr(g_cur1);
    int* cur2 = (int*)symaddr(g_cur2);
    int* col1 = (int*)symaddr(g_col1);
    int* col2 = (int*)symaddr(g_col2);
    fp16* wt = (fp16*)symaddr(g_wt);

    const int TB = 256;
    const int gN = (NN + TB - 1) / TB;
    const int gE = (EE + TB - 1) / TB;

    // --- input conversion + weight transpose ---
    const int n4 = NN * FF / 4;
    k_f2h<<<(n4 + 255) / 256, 256>>>(x,  xb1, n4);
    k_f2h<<<(n4 + 255) / 256, 256>>>(x1, xb2, n4);
    k_wt<<<(FF * HH + 255) / 256, 256>>>(Wg1, wt + OWG1, FF, HH);
    k_wt<<<(FF * HH + 255) / 256, 256>>>(Wg2, wt + OWG2, FF, HH);
    k_wt<<<(HH * HG + 255) / 256, 256>>>(Wl1, wt + OWL1, HH, HG);
    k_wt<<<(HH * HG + 255) / 256, 256>>>(Wr1, wt + OWR1, HH, HG);
    k_wt<<<(HH * HG + 255) / 256, 256>>>(Wl2, wt + OWL2, HH, HG);
    k_wt<<<(HH * HG + 255) / 256, 256>>>(Wr2, wt + OWR2, HH, HG);
    k_wt<<<(HG * HG + 255) / 256, 256>>>(Wm1, wt + OWM1, HG, HG);

    // --- build CSR for both graphs ---
    k_zero_int<<<gN, TB>>>(deg1, NN);
    k_zero_int<<<gN, TB>>>(deg2, NN);
    k_deg<<<gE, TB>>>(dst1, deg1);
    k_deg<<<gE, TB>>>(dst2, deg2);
    k_scan<<<1, 1024>>>(deg1, rp1, NN);
    k_scan<<<1, 1024>>>(deg2, rp2, NN);
    k_disinv<<<gN, TB>>>(deg1, dis1, inv1);
    k_disinv<<<gN, TB>>>(deg2, dis2, inv2);
    k_copy_int<<<gN, TB>>>(cur1, rp1, NN);
    k_copy_int<<<gN, TB>>>(cur2, rp2, NN);
    k_place<<<gE, TB>>>(src1, dst1, cur1, col1);
    k_place<<<gE, TB>>>(src2, dst2, cur2, col2);

    // --- MMA GEMM setup ---
    cudaFuncSetAttribute(k_mma, cudaFuncAttributeMaxDynamicSharedMemorySize, SMEM_MMA);
    const int GY = (NN + 127) / 128;  // 782
    dim3 g256(HH / 128, GY);
    dim3 g128(HG / 128, GY);

    // --- GCN layer: XW = x @ Wg ---
    k_mma<<<g256, 256, SMEM_MMA>>>(xb1, wt + OWG1, FF, nullptr, nullptr, 0,
                                   XW1, HH, nullptr, 0);
    k_mma<<<g256, 256, SMEM_MMA>>>(xb2, wt + OWG2, FF, nullptr, nullptr, 0,
                                   XW2, HH, nullptr, 0);

    const int gW = NN / 8;
    k_gcn<<<gW, 256>>>(XW1, rp1, col1, dis1, bg1, 0);
    k_gcn<<<gW, 256>>>(XW2, rp2, col2, dis2, bg2, 1);

    // --- branch A: SAGE(graph1, X0) -> MLP ---
    k_sage<<<gW, 256>>>(X0, rp1, col1, inv1);
    k_mma<<<g128, 256, SMEM_MMA>>>(MEAN, wt + OWL1, HH, X0, wt + OWR1, HH,
                                   A1, HG, bl1, 1);
    k_mma<<<g128, 256, SMEM_MMA>>>(A1, wt + OWM1, HG, nullptr, nullptr, 0,
                                   MEAN, HG, bm1, 0);
    k_lndot<<<gW, 256>>>(MEAN, lnw, lnb, Wm2, bm2, 0);

    // --- branch B: SAGE(graph2, G1) -> MLP ---
    k_sage<<<gW, 256>>>(G1, rp2, col2, inv2);
    k_mma<<<g128, 256, SMEM_MMA>>>(MEAN, wt + OWL2, HH, G1, wt + OWR2, HH,
                                   A1, HG, bl2, 1);
    k_mma<<<g128, 256, SMEM_MMA>>>(A1, wt + OWM1, HG, nullptr, nullptr, 0,
                                   MEAN, HG, bm1, 0);
    k_lndot<<<gW, 256>>>(MEAN, lnw, lnb, Wm2, bm2, NN / 8);

    k_final<<<1, 1024>>>((float*)d_out);
}

// round 6
// speedup vs baseline: 3.6019x; 1.0858x over previous
#include <cuda_runtime.h>
#include <cuda_fp16.h>
#include <cstdint>

#define NN 100000
#define EE 600000
#define FF 512
#define HH 256
#define HG 128   // H2

typedef __half fp16;
typedef __half2 fp162;

// ---------------- scratch (static __device__ — no allocations) ----------------
__device__ fp16 g_xb1[(size_t)NN * FF];
__device__ fp16 g_xb2[(size_t)NN * FF];
__device__ fp16 g_XW1[(size_t)NN * HH];   // later reused as branch-B MEAN / T
__device__ fp16 g_XW2[(size_t)NN * HH];   // later reused as branch-B A1
__device__ fp16 g_X0 [(size_t)NN * HH];
__device__ fp16 g_G1 [(size_t)NN * HH];
__device__ fp16 g_MEAN[(size_t)NN * HH];  // branch-A MEAN / T
__device__ fp16 g_A1 [(size_t)NN * HG];   // branch-A A1
__device__ float g_dis1[NN], g_dis2[NN], g_inv1[NN], g_inv2[NN];
__device__ int   g_deg1[NN], g_deg2[NN];
__device__ int   g_rp1[NN + 1], g_rp2[NN + 1];
__device__ int   g_cur1[NN + 1], g_cur2[NN + 1];
__device__ int   g_col1[EE], g_col2[EE];
__device__ float g_part[25000];

// pre-transposed fp16 weights, layout WT[n*K + k]
#define OWG1 0
#define OWG2 131072
#define OWL1 262144
#define OWR1 294912
#define OWL2 327680
#define OWR2 360448
#define OWM1 393216
__device__ fp16 g_wt[409600];

// ---------------- conversion kernels ----------------
__global__ void k_f2h(const float* __restrict__ in, fp16* __restrict__ out, int n4) {
    int i = blockIdx.x * blockDim.x + threadIdx.x;
    if (i < n4) {
        float4 v = ((const float4*)in)[i];
        fp162 a = __float22half2_rn(make_float2(v.x, v.y));
        fp162 b = __float22half2_rn(make_float2(v.z, v.w));
        ((uint2*)out)[i] = make_uint2(*(uint32_t*)&a, *(uint32_t*)&b);
    }
}

__global__ void k_wt(const float* __restrict__ W, fp16* __restrict__ th, int K, int M) {
    int i = blockIdx.x * blockDim.x + threadIdx.x;
    if (i < K * M) {
        int k = i / M, n = i % M;
        th[(size_t)n * K + k] = __float2half(W[i]);
    }
}

// ---------------- MMA GEMM: C[NN,M] = A1@W1 (+ A2@W2) (+bias)(relu), fp16 -------
#define LDSB 80          // bytes per smem row (32 fp16 = 64B + 16B pad)
#define STG_T 10240      // 128 rows * 80B
#define OFF_A  0
#define OFF_B  20480
#define SMEM_MMA 40960

__device__ __forceinline__ void cpa16(uint32_t dst, const void* src) {
    asm volatile("cp.async.ca.shared.global [%0], [%1], 16;"
                 :: "r"(dst), "l"(src));
}

__device__ __forceinline__ void mma_fp16(float* c, const uint32_t* a, const uint32_t* b) {
    asm volatile(
        "mma.sync.aligned.m16n8k16.row.col.f32.f16.f16.f32 "
        "{%0,%1,%2,%3}, {%4,%5,%6,%7}, {%8,%9}, {%0,%1,%2,%3};"
        : "+f"(c[0]), "+f"(c[1]), "+f"(c[2]), "+f"(c[3])
        : "r"(a[0]), "r"(a[1]), "r"(a[2]), "r"(a[3]), "r"(b[0]), "r"(b[1]));
}

__global__ void __launch_bounds__(256, 2)
k_mma(const fp16* __restrict__ A1p, const fp16* __restrict__ W1, int K1,
      const fp16* __restrict__ A2p, const fp16* __restrict__ W2, int K2,
      fp16* __restrict__ C, int M,
      const float* __restrict__ bias, int reluflag)
{
    extern __shared__ __align__(16) char smem[];
    const uint32_t sb = (uint32_t)__cvta_generic_to_shared(smem);
    const int tid = threadIdx.x;
    const int wid = tid >> 5, lane = tid & 31;
    const int warp_m = wid & 1, warp_n = wid >> 1;
    const int rowBase = blockIdx.y * 128;
    const int colBase = blockIdx.x * 128;

    const int n1 = K1 >> 5;
    const int n2 = A2p ? (K2 >> 5) : 0;
    const int total = n1 + n2;

    float acc[4][4][4];
#pragma unroll
    for (int i = 0; i < 4; i++)
#pragma unroll
        for (int j = 0; j < 4; j++)
#pragma unroll
            for (int q = 0; q < 4; q++) acc[i][j][q] = 0.0f;

    auto pick = [&](int it, const fp16*& A, const fp16*& W, int& K, int& k0) {
        if (it < n1) { A = A1p; W = W1; K = K1; k0 = it << 5; }
        else         { A = A2p; W = W2; K = K2; k0 = (it - n1) << 5; }
    };

    auto issue = [&](int it, int stage) {
        const fp16 *A, *W; int K, k0;
        pick(it, A, W, K, k0);
#pragma unroll
        for (int i = 0; i < 2; i++) {
            int idx = tid + i * 256;
            int r = idx >> 2, part = idx & 3;
            int gr = rowBase + r;
            uint32_t d = sb + OFF_A + stage * STG_T + r * LDSB + part * 16;
            if (gr < NN) cpa16(d, A + (size_t)gr * K + k0 + part * 8);
            else asm volatile("st.shared.v4.b32 [%0], {%1,%1,%1,%1};" :: "r"(d), "r"(0));
        }
#pragma unroll
        for (int i = 0; i < 2; i++) {
            int idx = tid + i * 256;
            int n = idx >> 2, part = idx & 3;
            int gn = colBase + n;
            uint32_t d = sb + OFF_B + stage * STG_T + n * LDSB + part * 16;
            cpa16(d, W + (size_t)gn * K + k0 + part * 8);
        }
        asm volatile("cp.async.commit_group;");
    };

    auto compute = [&](int stage) {
#pragma unroll
        for (int ks = 0; ks < 2; ks++) {
            const int kk = ks * 16;
            uint32_t af[4][4];
#pragma unroll
            for (int mi = 0; mi < 4; mi++) {
                int row = warp_m * 64 + mi * 16 + (lane & 15);
                int kc = kk + ((lane >> 4) << 3);
                uint32_t ad = sb + OFF_A + stage * STG_T + row * LDSB + kc * 2;
                asm volatile("ldmatrix.sync.aligned.m8n8.x4.shared.b16 "
                             "{%0,%1,%2,%3}, [%4];"
                             : "=r"(af[mi][0]), "=r"(af[mi][1]),
                               "=r"(af[mi][2]), "=r"(af[mi][3]) : "r"(ad));
            }
            uint32_t bh[4][2];
#pragma unroll
            for (int ni = 0; ni < 4; ni++) {
                int rn = warp_n * 32 + ni * 8 + (lane & 7);
                int kc = kk + ((lane >> 3) & 1) * 8;
                uint32_t off = sb + OFF_B + stage * STG_T + rn * LDSB + kc * 2;
                asm volatile("ldmatrix.sync.aligned.m8n8.x2.shared.b16 {%0,%1}, [%2];"
                             : "=r"(bh[ni][0]), "=r"(bh[ni][1]) : "r"(off));
            }
#pragma unroll
            for (int mi = 0; mi < 4; mi++)
#pragma unroll
                for (int ni = 0; ni < 4; ni++)
                    mma_fp16(acc[mi][ni], af[mi], bh[ni]);
        }
    };

    issue(0, 0);
    asm volatile("cp.async.wait_group 0;");
    __syncthreads();

    int stage = 0;
    for (int it = 0; it < total; ++it) {
        if (it + 1 < total) issue(it + 1, stage ^ 1);
        compute(stage);
        if (it + 1 < total) asm volatile("cp.async.wait_group 0;");
        __syncthreads();
        stage ^= 1;
    }

    const int g = lane >> 2, tg = lane & 3;
#pragma unroll
    for (int mi = 0; mi < 4; mi++) {
#pragma unroll
        for (int ni = 0; ni < 4; ni++) {
            int col = colBase + warp_n * 32 + ni * 8 + tg * 2;
            float b0 = 0.f, b1 = 0.f;
            if (bias) { b0 = bias[col]; b1 = bias[col + 1]; }
            int row = rowBase + warp_m * 64 + mi * 16 + g;
            if (row < NN) {
                float vx = acc[mi][ni][0] + b0, vy = acc[mi][ni][1] + b1;
                if (reluflag) { vx = fmaxf(vx, 0.f); vy = fmaxf(vy, 0.f); }
                fp162 h = __float22half2_rn(make_float2(vx, vy));
                *(fp162*)(C + (size_t)row * M + col) = h;
            }
            if (row + 8 < NN) {
                float vx = acc[mi][ni][2] + b0, vy = acc[mi][ni][3] + b1;
                if (reluflag) { vx = fmaxf(vx, 0.f); vy = fmaxf(vy, 0.f); }
                fp162 h = __float22half2_rn(make_float2(vx, vy));
                *(fp162*)(C + (size_t)(row + 8) * M + col) = h;
            }
        }
    }
}

// ---------------- small utility kernels ----------------
__global__ void k_zero_int(int* p, int n) {
    int i = blockIdx.x * blockDim.x + threadIdx.x;
    if (i < n) p[i] = 0;
}

__global__ void k_copy_int(int* dst, const int* src, int n) {
    int i = blockIdx.x * blockDim.x + threadIdx.x;
    if (i < n) dst[i] = src[i];
}

__global__ void k_deg(const int* __restrict__ dst, int* __restrict__ deg) {
    int e = blockIdx.x * blockDim.x + threadIdx.x;
    if (e < EE) atomicAdd(&deg[dst[e]], 1);
}

__global__ void k_scan(const int* __restrict__ deg, int* __restrict__ rp, int n) {
    __shared__ int s[1024];
    int t = threadIdx.x;
    int chunk = (n + 1023) >> 10;
    int b = t * chunk;
    int e = b + chunk; if (e > n) e = n;
    int local = 0;
    for (int i = b; i < e && i < n; i++) local += deg[i];
    s[t] = local;
    __syncthreads();
    for (int off = 1; off < 1024; off <<= 1) {
        int v = (t >= off) ? s[t - off] : 0;
        __syncthreads();
        s[t] += v;
        __syncthreads();
    }
    int run = (t == 0) ? 0 : s[t - 1];
    for (int i = b; i < e && i < n; i++) { rp[i] = run; run += deg[i]; }
    if (t == 1023) rp[n] = s[1023];
}

__global__ void k_disinv(const int* __restrict__ deg, float* __restrict__ dis,
                         float* __restrict__ inv) {
    int i = blockIdx.x * blockDim.x + threadIdx.x;
    if (i < NN) {
        float d = (float)deg[i];
        dis[i] = rsqrtf(d + 1.0f);
        inv[i] = 1.0f / fmaxf(d, 1.0f);
    }
}

__global__ void k_place(const int* __restrict__ src, const int* __restrict__ dst,
                        int* __restrict__ cur, int* __restrict__ col) {
    int e = blockIdx.x * blockDim.x + threadIdx.x;
    if (e < EE) {
        int d = dst[e];
        int p = atomicAdd(&cur[d], 1);
        col[p] = src[e];
    }
}

// ---------------- helpers for fp16 gather ----------------
__device__ __forceinline__ void unp8(uint4 v, float* f) {
    float2 a = __half22float2(*(fp162*)&v.x);
    float2 b = __half22float2(*(fp162*)&v.y);
    float2 c = __half22float2(*(fp162*)&v.z);
    float2 d = __half22float2(*(fp162*)&v.w);
    f[0] = a.x; f[1] = a.y; f[2] = b.x; f[3] = b.y;
    f[4] = c.x; f[5] = c.y; f[6] = d.x; f[7] = d.y;
}

__device__ __forceinline__ uint4 pk8(const float* f) {
    fp162 a = __float22half2_rn(make_float2(f[0], f[1]));
    fp162 b = __float22half2_rn(make_float2(f[2], f[3]));
    fp162 c = __float22half2_rn(make_float2(f[4], f[5]));
    fp162 d = __float22half2_rn(make_float2(f[6], f[7]));
    return make_uint4(*(uint32_t*)&a, *(uint32_t*)&b, *(uint32_t*)&c, *(uint32_t*)&d);
}

// ---------------- GCN aggregation (warp per node, gather over CSR, fp16) ----------
__global__ void k_gcn(const fp16* __restrict__ xw, const int* __restrict__ rp,
                      const int* __restrict__ col, const float* __restrict__ dis,
                      const float* __restrict__ bias, int mode) {
    int node = blockIdx.x * 8 + (threadIdx.x >> 5);
    int lane = threadIdx.x & 31;
    if (node >= NN) return;

    const uint4* xw4 = (const uint4*)xw;
    float acc[8] = {0, 0, 0, 0, 0, 0, 0, 0};
    int e0 = rp[node], e1 = rp[node + 1];
    for (int e = e0; e < e1; e++) {
        int s = col[e];
        float ds = dis[s];
        float f[8];
        unp8(xw4[(size_t)s * 32 + lane], f);
#pragma unroll
        for (int u = 0; u < 8; u++) acc[u] += f[u] * ds;
    }
    float di = dis[node];
    float dii = di * di;
    float sf[8];
    unp8(xw4[(size_t)node * 32 + lane], sf);
    const float4* b4 = (const float4*)bias;
    float4 bb0 = b4[2 * lane], bb1 = b4[2 * lane + 1];
    float bb[8] = {bb0.x, bb0.y, bb0.z, bb0.w, bb1.x, bb1.y, bb1.z, bb1.w};

    float v[8], r[8];
#pragma unroll
    for (int u = 0; u < 8; u++) {
        v[u] = acc[u] * di + sf[u] * dii + bb[u];
        r[u] = fmaxf(v[u], 0.f);
    }

    size_t o = (size_t)node * 32 + lane;
    uint4* X04 = (uint4*)g_X0;
    if (mode == 0) {
        X04[o] = pk8(r);
    } else {
        float xs[8];
        unp8(X04[o], xs);
#pragma unroll
        for (int u = 0; u < 8; u++) xs[u] += r[u];
        X04[o] = pk8(xs);
        float gg[8];
#pragma unroll
        for (int u = 0; u < 8; u++) gg[u] = r[u] + v[u];
        ((uint4*)g_G1)[o] = pk8(gg);
    }
}

// ---------------- SAGE mean aggregation (warp per node, fp16) ----------
__global__ void k_sage(const fp16* __restrict__ feat, const int* __restrict__ rp,
                       const int* __restrict__ col, const float* __restrict__ inv,
                       fp16* __restrict__ out) {
    int node = blockIdx.x * 8 + (threadIdx.x >> 5);
    int lane = threadIdx.x & 31;
    if (node >= NN) return;

    const uint4* f4 = (const uint4*)feat;
    float acc[8] = {0, 0, 0, 0, 0, 0, 0, 0};
    int e0 = rp[node], e1 = rp[node + 1];
    for (int e = e0; e < e1; e++) {
        int s = col[e];
        float f[8];
        unp8(f4[(size_t)s * 32 + lane], f);
#pragma unroll
        for (int u = 0; u < 8; u++) acc[u] += f[u];
    }
    float ic = inv[node];
#pragma unroll
    for (int u = 0; u < 8; u++) acc[u] *= ic;
    ((uint4*)out)[(size_t)node * 32 + lane] = pk8(acc);
}

// ---------------- LayerNorm + final dot, warp per row (fp16 T) ----------------
__device__ __forceinline__ float warp_sum(float v) {
#pragma unroll
    for (int o = 16; o; o >>= 1) v += __shfl_xor_sync(0xffffffffu, v, o);
    return v;
}

__global__ void k_lndot(const fp16* __restrict__ T, const float* __restrict__ lnw,
                        const float* __restrict__ lnb, const float* __restrict__ wm2,
                        const float* __restrict__ bm2, int poff) {
    __shared__ float ws[8];
    int wid = threadIdx.x >> 5, lane = threadIdx.x & 31;
    int row = blockIdx.x * 8 + wid;
    float y = 0.0f;
    if (row < NN) {
        uint2 tv = ((const uint2*)T)[(size_t)row * 32 + lane];
        float2 t01 = __half22float2(*(fp162*)&tv.x);
        float2 t23 = __half22float2(*(fp162*)&tv.y);
        float sum = t01.x + t01.y + t23.x + t23.y;
        float sq = t01.x * t01.x + t01.y * t01.y + t23.x * t23.x + t23.y * t23.y;
        sum = warp_sum(sum);
        sq = warp_sum(sq);
        float mu = sum * (1.0f / 128.0f);
        float var = sq * (1.0f / 128.0f) - mu * mu;
        float rs = rsqrtf(var + 1e-5f);
        float4 w = ((const float4*)lnw)[lane];
        float4 b = ((const float4*)lnb)[lane];
        float4 m = ((const float4*)wm2)[lane];
        float p = ((t01.x - mu) * rs * w.x + b.x) * m.x
                + ((t01.y - mu) * rs * w.y + b.y) * m.y
                + ((t23.x - mu) * rs * w.z + b.z) * m.z
                + ((t23.y - mu) * rs * w.w + b.w) * m.w;
        p = warp_sum(p);
        y = p + bm2[0];
    }
    if (lane == 0) ws[wid] = y;
    __syncthreads();
    if (threadIdx.x == 0) {
        float s = 0;
#pragma unroll
        for (int i = 0; i < 8; i++) s += ws[i];
        g_part[poff + blockIdx.x] = s;
    }
}

__global__ void k_final(float* out) {
    __shared__ float s[1024];
    int t = threadIdx.x;
    float v = 0;
    for (int i = t; i < 25000; i += 1024) v += g_part[i];
    s[t] = v;
    __syncthreads();
    for (int off = 512; off; off >>= 1) {
        if (t < off) s[t] += s[t + off];
        __syncthreads();
    }
    if (t == 0) out[0] = s[0] * (1.0f / (2.0f * (float)NN));
}

// ---------------- host ----------------
static void* symaddr(const void* s) {
    void* p = nullptr;
    cudaGetSymbolAddress(&p, s);
    return p;
}

static cudaStream_t mkstream() {
    cudaStream_t s;
    cudaStreamCreateWithFlags(&s, cudaStreamNonBlocking);
    return s;
}
static cudaEvent_t mkevent() {
    cudaEvent_t e;
    cudaEventCreateWithFlags(&e, cudaEventDisableTiming);
    return e;
}

extern "C" void kernel_launch(void* const* d_in, const int* in_sizes, int n_in,
                              void* d_out, int out_size) {
    // streams/events created once on the first (uncaptured) correctness call
    static cudaStream_t s1 = mkstream();
    static cudaStream_t s2 = mkstream();
    static cudaEvent_t eF = mkevent();
    static cudaEvent_t e1 = mkevent();
    static cudaEvent_t e2 = mkevent();
    static cudaEvent_t eG = mkevent();
    static cudaEvent_t eB = mkevent();

    const float* x   = (const float*)d_in[0];
    const float* x1  = (const float*)d_in[1];
    const int*   ei  = (const int*)d_in[2];
    const int*   ei1 = (const int*)d_in[3];
    const float* Wg1 = (const float*)d_in[4];
    const float* bg1 = (const float*)d_in[5];
    const float* Wg2 = (const float*)d_in[6];
    const float* bg2 = (const float*)d_in[7];
    const float* Wl1 = (const float*)d_in[8];
    const float* bl1 = (const float*)d_in[9];
    const float* Wr1 = (const float*)d_in[10];
    const float* Wl2 = (const float*)d_in[11];
    const float* bl2 = (const float*)d_in[12];
    const float* Wr2 = (const float*)d_in[13];
    const float* Wm1 = (const float*)d_in[14];
    const float* bm1 = (const float*)d_in[15];
    const float* lnw = (const float*)d_in[16];
    const float* lnb = (const float*)d_in[17];
    const float* Wm2 = (const float*)d_in[18];
    const float* bm2 = (const float*)d_in[19];

    const int* src1 = ei;
    const int* dst1 = ei + EE;
    const int* src2 = ei1;
    const int* dst2 = ei1 + EE;

    fp16* xb1  = (fp16*)symaddr(g_xb1);
    fp16* xb2  = (fp16*)symaddr(g_xb2);
    fp16* XW1  = (fp16*)symaddr(g_XW1);
    fp16* XW2  = (fp16*)symaddr(g_XW2);
    fp16* X0   = (fp16*)symaddr(g_X0);
    fp16* G1   = (fp16*)symaddr(g_G1);
    fp16* MEAN = (fp16*)symaddr(g_MEAN);
    fp16* A1   = (fp16*)symaddr(g_A1);
    float* dis1 = (float*)symaddr(g_dis1);
    float* dis2 = (float*)symaddr(g_dis2);
    float* inv1 = (float*)symaddr(g_inv1);
    float* inv2 = (float*)symaddr(g_inv2);
    int* deg1 = (int*)symaddr(g_deg1);
    int* deg2 = (int*)symaddr(g_deg2);
    int* rp1  = (int*)symaddr(g_rp1);
    int* rp2  = (int*)symaddr(g_rp2);
    int* cur1 = (int*)symaddr(g_cur1);
    int* cur2 = (int*)symaddr(g_cur2);
    int* col1 = (int*)symaddr(g_col1);
    int* col2 = (int*)symaddr(g_col2);
    fp16* wt = (fp16*)symaddr(g_wt);

    // branch-B buffers reuse XW1/XW2 (dead after gcn2)
    fp16* MEANB = XW1;
    fp16* A1B   = XW2;

    const int TB = 256;
    const int gN = (NN + TB - 1) / TB;
    const int gE = (EE + TB - 1) / TB;
    const int n4 = NN * FF / 4;

    cudaFuncSetAttribute(k_mma, cudaFuncAttributeMaxDynamicSharedMemorySize, SMEM_MMA);
    const int GY = (NN + 127) / 128;  // 782
    dim3 g256(HH / 128, GY);
    dim3 g128(HG / 128, GY);
    const int gW = NN / 8;

    // ---- fork ----
    cudaEventRecord(eF, 0);
    cudaStreamWaitEvent(s1, eF, 0);
    cudaStreamWaitEvent(s2, eF, 0);

    // ---- s0: graph-1 GEMM path ----
    k_wt<<<(FF * HH + 255) / 256, 256, 0, 0>>>(Wg1, wt + OWG1, FF, HH);
    k_f2h<<<(n4 + 255) / 256, 256, 0, 0>>>(x, xb1, n4);
    k_mma<<<g256, 256, SMEM_MMA, 0>>>(xb1, wt + OWG1, FF, nullptr, nullptr, 0,
                                      XW1, HH, nullptr, 0);

    // ---- s1: graph-2 GEMM path ----
    k_wt<<<(FF * HH + 255) / 256, 256, 0, s1>>>(Wg2, wt + OWG2, FF, HH);
    k_f2h<<<(n4 + 255) / 256, 256, 0, s1>>>(x1, xb2, n4);
    k_mma<<<g256, 256, SMEM_MMA, s1>>>(xb2, wt + OWG2, FF, nullptr, nullptr, 0,
                                       XW2, HH, nullptr, 0);
    cudaEventRecord(e1, s1);

    // ---- s2: CSR build (both graphs) + SAGE/MLP weight transposes ----
    k_wt<<<(HH * HG + 255) / 256, 256, 0, s2>>>(Wl1, wt + OWL1, HH, HG);
    k_wt<<<(HH * HG + 255) / 256, 256, 0, s2>>>(Wr1, wt + OWR1, HH, HG);
    k_wt<<<(HH * HG + 255) / 256, 256, 0, s2>>>(Wl2, wt + OWL2, HH, HG);
    k_wt<<<(HH * HG + 255) / 256, 256, 0, s2>>>(Wr2, wt + OWR2, HH, HG);
    k_wt<<<(HG * HG + 255) / 256, 256, 0, s2>>>(Wm1, wt + OWM1, HG, HG);
    k_zero_int<<<gN, TB, 0, s2>>>(deg1, NN);
    k_zero_int<<<gN, TB, 0, s2>>>(deg2, NN);
    k_deg<<<gE, TB, 0, s2>>>(dst1, deg1);
    k_deg<<<gE, TB, 0, s2>>>(dst2, deg2);
    k_scan<<<1, 1024, 0, s2>>>(deg1, rp1, NN);
    k_scan<<<1, 1024, 0, s2>>>(deg2, rp2, NN);
    k_disinv<<<gN, TB, 0, s2>>>(deg1, dis1, inv1);
    k_disinv<<<gN, TB, 0, s2>>>(deg2, dis2, inv2);
    k_copy_int<<<gN, TB, 0, s2>>>(cur1, rp1, NN);
    k_copy_int<<<gN, TB, 0, s2>>>(cur2, rp2, NN);
    k_place<<<gE, TB, 0, s2>>>(src1, dst1, cur1, col1);
    k_place<<<gE, TB, 0, s2>>>(src2, dst2, cur2, col2);
    cudaEventRecord(e2, s2);

    // ---- s0: GCN aggregations (serial RMW on X0) ----
    cudaStreamWaitEvent(0, e2, 0);
    k_gcn<<<gW, 256, 0, 0>>>(XW1, rp1, col1, dis1, bg1, 0);
    cudaStreamWaitEvent(0, e1, 0);
    k_gcn<<<gW, 256, 0, 0>>>(XW2, rp2, col2, dis2, bg2, 1);
    cudaEventRecord(eG, 0);

    // ---- branch A on s0: SAGE(graph1, X0) -> MLP ----
    k_sage<<<gW, 256, 0, 0>>>(X0, rp1, col1, inv1, MEAN);
    k_mma<<<g128, 256, SMEM_MMA, 0>>>(MEAN, wt + OWL1, HH, X0, wt + OWR1, HH,
                                      A1, HG, bl1, 1);
    k_mma<<<g128, 256, SMEM_MMA, 0>>>(A1, wt + OWM1, HG, nullptr, nullptr, 0,
                                      MEAN, HG, bm1, 0);
    k_lndot<<<gW, 256, 0, 0>>>(MEAN, lnw, lnb, Wm2, bm2, 0);

    // ---- branch B on s1: SAGE(graph2, G1) -> MLP ----
    cudaStreamWaitEvent(s1, eG, 0);
    k_sage<<<gW, 256, 0, s1>>>(G1, rp2, col2, inv2, MEANB);
    k_mma<<<g128, 256, SMEM_MMA, s1>>>(MEANB, wt + OWL2, HH, G1, wt + OWR2, HH,
                                       A1B, HG, bl2, 1);
    k_mma<<<g128, 256, SMEM_MMA, s1>>>(A1B, wt + OWM1, HG, nullptr, nullptr, 0,
                                       MEANB, HG, bm1, 0);
    k_lndot<<<gW, 256, 0, s1>>>(MEANB, lnw, lnb, Wm2, bm2, NN / 8);
    cudaEventRecord(eB, s1);

    // ---- join + final reduction ----
    cudaStreamWaitEvent(0, eB, 0);
    k_final<<<1, 1024, 0, 0>>>((float*)d_out);
}

// round 7
// speedup vs baseline: 3.7536x; 1.0421x over previous
#include <cuda_runtime.h>
#include <cuda_fp16.h>
#include <cstdint>

#define NN 100000
#define EE 600000
#define FF 512
#define HH 256
#define HG 128   // H2

typedef __half fp16;
typedef __half2 fp162;

// ---------------- scratch (static __device__ — no allocations) ----------------
__device__ fp16 g_XW1[(size_t)NN * HH];   // later reused as branch-B MEAN
__device__ fp16 g_XW2[(size_t)NN * HH];   // later reused as branch-B A1
__device__ fp16 g_X0 [(size_t)NN * HH];
__device__ fp16 g_G1 [(size_t)NN * HH];
__device__ fp16 g_MEAN[(size_t)NN * HH];  // branch-A MEAN
__device__ fp16 g_A1 [(size_t)NN * HG];   // branch-A A1
__device__ float g_dis1[NN], g_dis2[NN], g_inv1[NN], g_inv2[NN];
__device__ int   g_deg1[NN], g_deg2[NN];
__device__ int   g_rp1[NN + 1], g_rp2[NN + 1];
__device__ int   g_cur1[NN + 1], g_cur2[NN + 1];
__device__ int   g_col1[EE], g_col2[EE];
__device__ float g_part[1600];

// pre-transposed fp16 weights, layout WT[n*K + k]
#define OWG1 0
#define OWG2 131072
#define OWL1 262144
#define OWR1 294912
#define OWL2 327680
#define OWR2 360448
#define OWM1 393216
__device__ fp16 g_wt[409600];

// ---------------- weight transpose ----------------
__global__ void k_wt(const float* __restrict__ W, fp16* __restrict__ th, int K, int M) {
    int i = blockIdx.x * blockDim.x + threadIdx.x;
    if (i < K * M) {
        int k = i / M, n = i % M;
        th[(size_t)n * K + k] = __float2half(W[i]);
    }
}

// ---------------- MMA GEMM ----------------
#define LDSB 80          // bytes per smem row (32 fp16 = 64B + 16B pad)
#define STG_T 10240      // 128 rows * 80B
#define OFF_A  0
#define OFF_B  20480
#define SMEM_MMA 40960

__device__ __forceinline__ void cpa16(uint32_t dst, const void* src) {
    asm volatile("cp.async.ca.shared.global [%0], [%1], 16;"
                 :: "r"(dst), "l"(src));
}

__device__ __forceinline__ void mma_fp16(float* c, const uint32_t* a, const uint32_t* b) {
    asm volatile(
        "mma.sync.aligned.m16n8k16.row.col.f32.f16.f16.f32 "
        "{%0,%1,%2,%3}, {%4,%5,%6,%7}, {%8,%9}, {%0,%1,%2,%3};"
        : "+f"(c[0]), "+f"(c[1]), "+f"(c[2]), "+f"(c[3])
        : "r"(a[0]), "r"(a[1]), "r"(a[2]), "r"(a[3]), "r"(b[0]), "r"(b[1]));
}

__device__ __forceinline__ uint32_t pkh(float a, float b) {
    fp162 h = __float22half2_rn(make_float2(a, b));
    return *(uint32_t*)&h;
}

// A32: A1v is fp32, converted in-kernel (A2 unused). LN: fused LayerNorm+dot epilogue.
template<bool A32, bool LN>
__global__ void __launch_bounds__(256, 2)
k_mma(const void* __restrict__ A1v, const fp16* __restrict__ W1, int K1,
      const fp16* __restrict__ A2p, const fp16* __restrict__ W2, int K2,
      fp16* __restrict__ C, int M,
      const float* __restrict__ bias, int reluflag,
      const float* __restrict__ lnw, const float* __restrict__ lnb,
      const float* __restrict__ wm2, const float* __restrict__ bm2, int poff)
{
    extern __shared__ __align__(16) char smem[];
    const uint32_t sb = (uint32_t)__cvta_generic_to_shared(smem);
    const int tid = threadIdx.x;
    const int wid = tid >> 5, lane = tid & 31;
    const int warp_m = wid & 1, warp_n = wid >> 1;
    const int rowBase = blockIdx.y * 128;
    const int colBase = blockIdx.x * 128;

    const int n1 = K1 >> 5;
    const int n2 = A2p ? (K2 >> 5) : 0;
    const int total = n1 + n2;

    float acc[4][4][4];
#pragma unroll
    for (int i = 0; i < 4; i++)
#pragma unroll
        for (int j = 0; j < 4; j++)
#pragma unroll
            for (int q = 0; q < 4; q++) acc[i][j][q] = 0.0f;

    uint32_t aregs[8];

    auto pick = [&](int it, const fp16*& A, const fp16*& W, int& K, int& k0) {
        if (it < n1) { A = (const fp16*)A1v; W = W1; K = K1; k0 = it << 5; }
        else         { A = A2p; W = W2; K = K2; k0 = (it - n1) << 5; }
    };

    auto issue = [&](int it, int stage) {
        const fp16 *A, *W; int K, k0;
        pick(it, A, W, K, k0);
        if (!A32) {
#pragma unroll
            for (int i = 0; i < 2; i++) {
                int idx = tid + i * 256;
                int r = idx >> 2, part = idx & 3;
                int gr = rowBase + r;
                uint32_t d = sb + OFF_A + stage * STG_T + r * LDSB + part * 16;
                if (gr < NN) cpa16(d, A + (size_t)gr * K + k0 + part * 8);
                else asm volatile("st.shared.v4.b32 [%0], {%1,%1,%1,%1};" :: "r"(d), "r"(0));
            }
        }
#pragma unroll
        for (int i = 0; i < 2; i++) {
            int idx = tid + i * 256;
            int n = idx >> 2, part = idx & 3;
            int gn = colBase + n;
            uint32_t d = sb + OFF_B + stage * STG_T + n * LDSB + part * 16;
            cpa16(d, W + (size_t)gn * K + k0 + part * 8);
        }
        asm volatile("cp.async.commit_group;");
    };

    auto loadAreg = [&](int it) {
        if (A32) {
            const float* Af = (const float*)A1v;
            int k0 = it << 5;
            int gr = rowBase + (tid >> 1);
            const float* p = Af + (size_t)gr * K1 + k0 + (tid & 1) * 16;
#pragma unroll
            for (int j = 0; j < 4; j++) {
                float4 v = (gr < NN) ? *(const float4*)(p + 4 * j)
                                     : make_float4(0.f, 0.f, 0.f, 0.f);
                aregs[2 * j] = pkh(v.x, v.y);
                aregs[2 * j + 1] = pkh(v.z, v.w);
            }
        }
    };

    auto storeAreg = [&](int stage) {
        if (A32) {
            uint32_t d = sb + OFF_A + stage * STG_T + (tid >> 1) * LDSB + (tid & 1) * 32;
#pragma unroll
            for (int j = 0; j < 8; j++)
                asm volatile("st.shared.b32 [%0], %1;" :: "r"(d + 4 * j), "r"(aregs[j]));
        }
    };

    auto compute = [&](int stage) {
#pragma unroll
        for (int ks = 0; ks < 2; ks++) {
            const int kk = ks * 16;
            uint32_t af[4][4];
#pragma unroll
            for (int mi = 0; mi < 4; mi++) {
                int row = warp_m * 64 + mi * 16 + (lane & 15);
                int kc = kk + ((lane >> 4) << 3);
                uint32_t ad = sb + OFF_A + stage * STG_T + row * LDSB + kc * 2;
                asm volatile("ldmatrix.sync.aligned.m8n8.x4.shared.b16 "
                             "{%0,%1,%2,%3}, [%4];"
                             : "=r"(af[mi][0]), "=r"(af[mi][1]),
                               "=r"(af[mi][2]), "=r"(af[mi][3]) : "r"(ad));
            }
            uint32_t bh[4][2];
#pragma unroll
            for (int ni = 0; ni < 4; ni++) {
                int rn = warp_n * 32 + ni * 8 + (lane & 7);
                int kc = kk + ((lane >> 3) & 1) * 8;
                uint32_t off = sb + OFF_B + stage * STG_T + rn * LDSB + kc * 2;
                asm volatile("ldmatrix.sync.aligned.m8n8.x2.shared.b16 {%0,%1}, [%2];"
                             : "=r"(bh[ni][0]), "=r"(bh[ni][1]) : "r"(off));
            }
#pragma unroll
            for (int mi = 0; mi < 4; mi++)
#pragma unroll
                for (int ni = 0; ni < 4; ni++)
                    mma_fp16(acc[mi][ni], af[mi], bh[ni]);
        }
    };

    issue(0, 0);
    loadAreg(0);
    storeAreg(0);
    asm volatile("cp.async.wait_group 0;");
    __syncthreads();

    int stage = 0;
    for (int it = 0; it < total; ++it) {
        if (it + 1 < total) { issue(it + 1, stage ^ 1); loadAreg(it + 1); }
        compute(stage);
        if (it + 1 < total) {
            storeAreg(stage ^ 1);
            asm volatile("cp.async.wait_group 0;");
        }
        __syncthreads();
        stage ^= 1;
    }

    const int g = lane >> 2, tg = lane & 3;

    if (!LN) {
        // ---- normal epilogue: fp16 out ----
#pragma unroll
        for (int mi = 0; mi < 4; mi++) {
#pragma unroll
            for (int ni = 0; ni < 4; ni++) {
                int col = colBase + warp_n * 32 + ni * 8 + tg * 2;
                float b0 = 0.f, b1 = 0.f;
                if (bias) { b0 = bias[col]; b1 = bias[col + 1]; }
                int row = rowBase + warp_m * 64 + mi * 16 + g;
                if (row < NN) {
                    float vx = acc[mi][ni][0] + b0, vy = acc[mi][ni][1] + b1;
                    if (reluflag) { vx = fmaxf(vx, 0.f); vy = fmaxf(vy, 0.f); }
                    fp162 h = __float22half2_rn(make_float2(vx, vy));
                    *(fp162*)(C + (size_t)row * M + col) = h;
                }
                if (row + 8 < NN) {
                    float vx = acc[mi][ni][2] + b0, vy = acc[mi][ni][3] + b1;
                    if (reluflag) { vx = fmaxf(vx, 0.f); vy = fmaxf(vy, 0.f); }
                    fp162 h = __float22half2_rn(make_float2(vx, vy));
                    *(fp162*)(C + (size_t)(row + 8) * M + col) = h;
                }
            }
        }
    } else {
        // ---- fused LayerNorm + dot(wm2) epilogue (M=128, gridDim.x=1) ----
        float* sred = (float*)smem;             // [128][8] sum/sq per warp_n
        float* sdot = (float*)(smem + 4096);    // [128][4] dot partials
        float* sblk = (float*)(smem + 6144);    // [4]

        float b0[4], b1[4], w0[4], w1[4], l0[4], l1[4], m0[4], m1[4];
#pragma unroll
        for (int ni = 0; ni < 4; ni++) {
            int c = warp_n * 32 + ni * 8 + tg * 2;
            b0[ni] = bias[c];  b1[ni] = bias[c + 1];
            w0[ni] = lnw[c];   w1[ni] = lnw[c + 1];
            l0[ni] = lnb[c];   l1[ni] = lnb[c + 1];
            m0[ni] = wm2[c];   m1[ni] = wm2[c + 1];
        }

        // pass 1: row partial sums
#pragma unroll
        for (int mi = 0; mi < 4; mi++) {
#pragma unroll
            for (int half = 0; half < 2; half++) {
                float ps = 0.f, pq = 0.f;
#pragma unroll
                for (int ni = 0; ni < 4; ni++) {
                    float v = acc[mi][ni][half * 2] + b0[ni];
                    float u = acc[mi][ni][half * 2 + 1] + b1[ni];
                    ps += v + u;
                    pq += v * v + u * u;
                }
                ps += __shfl_xor_sync(0xffffffffu, ps, 1);
                ps += __shfl_xor_sync(0xffffffffu, ps, 2);
                pq += __shfl_xor_sync(0xffffffffu, pq, 1);
                pq += __shfl_xor_sync(0xffffffffu, pq, 2);
                int r = warp_m * 64 + mi * 16 + g + half * 8;
                if (tg == 0) {
                    sred[r * 8 + warp_n * 2] = ps;
                    sred[r * 8 + warp_n * 2 + 1] = pq;
                }
            }
        }
        __syncthreads();

        // pass 2: normalize + dot
#pragma unroll
        for (int mi = 0; mi < 4; mi++) {
#pragma unroll
            for (int half = 0; half < 2; half++) {
                int r = warp_m * 64 + mi * 16 + g + half * 8;
                float sum = sred[r * 8 + 0] + sred[r * 8 + 2] + sred[r * 8 + 4] + sred[r * 8 + 6];
                float sq  = sred[r * 8 + 1] + sred[r * 8 + 3] + sred[r * 8 + 5] + sred[r * 8 + 7];
                float mu = sum * (1.0f / 128.0f);
                float var = sq * (1.0f / 128.0f) - mu * mu;
                float rs = rsqrtf(var + 1e-5f);
                float p = 0.f;
#pragma unroll
                for (int ni = 0; ni < 4; ni++) {
                    float v = acc[mi][ni][half * 2] + b0[ni];
                    float u = acc[mi][ni][half * 2 + 1] + b1[ni];
                    p += ((v - mu) * rs * w0[ni] + l0[ni]) * m0[ni]
                       + ((u - mu) * rs * w1[ni] + l1[ni]) * m1[ni];
                }
                p += __shfl_xor_sync(0xffffffffu, p, 1);
                p += __shfl_xor_sync(0xffffffffu, p, 2);
                if (tg == 0) sdot[r * 4 + warp_n] = p;
            }
        }
        __syncthreads();

        // pass 3: per-CTA partial of sum over valid rows
        if (tid < 128) {
            int r = tid;
            int grow = rowBase + r;
            float y = 0.f;
            if (grow < NN)
                y = sdot[r * 4] + sdot[r * 4 + 1] + sdot[r * 4 + 2] + sdot[r * 4 + 3] + bm2[0];
#pragma unroll
            for (int o = 16; o; o >>= 1) y += __shfl_xor_sync(0xffffffffu, y, o);
            if ((tid & 31) == 0) sblk[tid >> 5] = y;
        }
        __syncthreads();
        if (tid == 0)
            g_part[poff + blockIdx.y] = sblk[0] + sblk[1] + sblk[2] + sblk[3];
    }
}

// ---------------- small utility kernels ----------------
__global__ void k_zero_int(int* p, int n) {
    int i = blockIdx.x * blockDim.x + threadIdx.x;
    if (i < n) p[i] = 0;
}

__global__ void k_copy_int(int* dst, const int* src, int n) {
    int i = blockIdx.x * blockDim.x + threadIdx.x;
    if (i < n) dst[i] = src[i];
}

__global__ void k_deg(const int* __restrict__ dst, int* __restrict__ deg) {
    int e = blockIdx.x * blockDim.x + threadIdx.x;
    if (e < EE) atomicAdd(&deg[dst[e]], 1);
}

__global__ void k_scan(const int* __restrict__ deg, int* __restrict__ rp, int n) {
    __shared__ int s[1024];
    int t = threadIdx.x;
    int chunk = (n + 1023) >> 10;
    int b = t * chunk;
    int e = b + chunk; if (e > n) e = n;
    int local = 0;
    for (int i = b; i < e && i < n; i++) local += deg[i];
    s[t] = local;
    __syncthreads();
    for (int off = 1; off < 1024; off <<= 1) {
        int v = (t >= off) ? s[t - off] : 0;
        __syncthreads();
        s[t] += v;
        __syncthreads();
    }
    int run = (t == 0) ? 0 : s[t - 1];
    for (int i = b; i < e && i < n; i++) { rp[i] = run; run += deg[i]; }
    if (t == 1023) rp[n] = s[1023];
}

__global__ void k_disinv(const int* __restrict__ deg, float* __restrict__ dis,
                         float* __restrict__ inv) {
    int i = blockIdx.x * blockDim.x + threadIdx.x;
    if (i < NN) {
        float d = (float)deg[i];
        dis[i] = rsqrtf(d + 1.0f);
        inv[i] = 1.0f / fmaxf(d, 1.0f);
    }
}

__global__ void k_place(const int* __restrict__ src, const int* __restrict__ dst,
                        int* __restrict__ cur, int* __restrict__ col) {
    int e = blockIdx.x * blockDim.x + threadIdx.x;
    if (e < EE) {
        int d = dst[e];
        int p = atomicAdd(&cur[d], 1);
        col[p] = src[e];
    }
}

// ---------------- helpers for fp16 gather ----------------
__device__ __forceinline__ void unp8(uint4 v, float* f) {
    float2 a = __half22float2(*(fp162*)&v.x);
    float2 b = __half22float2(*(fp162*)&v.y);
    float2 c = __half22float2(*(fp162*)&v.z);
    float2 d = __half22float2(*(fp162*)&v.w);
    f[0] = a.x; f[1] = a.y; f[2] = b.x; f[3] = b.y;
    f[4] = c.x; f[5] = c.y; f[6] = d.x; f[7] = d.y;
}

__device__ __forceinline__ uint4 pk8(const float* f) {
    fp162 a = __float22half2_rn(make_float2(f[0], f[1]));
    fp162 b = __float22half2_rn(make_float2(f[2], f[3]));
    fp162 c = __float22half2_rn(make_float2(f[4], f[5]));
    fp162 d = __float22half2_rn(make_float2(f[6], f[7]));
    return make_uint4(*(uint32_t*)&a, *(uint32_t*)&b, *(uint32_t*)&c, *(uint32_t*)&d);
}

// ---------------- GCN aggregation (warp per node, gather over CSR, fp16) ----------
__global__ void k_gcn(const fp16* __restrict__ xw, const int* __restrict__ rp,
                      const int* __restrict__ col, const float* __restrict__ dis,
                      const float* __restrict__ bias, int mode) {
    int node = blockIdx.x * 8 + (threadIdx.x >> 5);
    int lane = threadIdx.x & 31;
    if (node >= NN) return;

    const uint4* xw4 = (const uint4*)xw;
    float acc[8] = {0, 0, 0, 0, 0, 0, 0, 0};
    int e0 = rp[node], e1 = rp[node + 1];
    for (int e = e0; e < e1; e++) {
        int s = col[e];
        float ds = dis[s];
        float f[8];
        unp8(xw4[(size_t)s * 32 + lane], f);
#pragma unroll
        for (int u = 0; u < 8; u++) acc[u] += f[u] * ds;
    }
    float di = dis[node];
    float dii = di * di;
    float sf[8];
    unp8(xw4[(size_t)node * 32 + lane], sf);
    const float4* b4 = (const float4*)bias;
    float4 bb0 = b4[2 * lane], bb1 = b4[2 * lane + 1];
    float bb[8] = {bb0.x, bb0.y, bb0.z, bb0.w, bb1.x, bb1.y, bb1.z, bb1.w};

    float v[8], r[8];
#pragma unroll
    for (int u = 0; u < 8; u++) {
        v[u] = acc[u] * di + sf[u] * dii + bb[u];
        r[u] = fmaxf(v[u], 0.f);
    }

    size_t o = (size_t)node * 32 + lane;
    uint4* X04 = (uint4*)g_X0;
    if (mode == 0) {
        X04[o] = pk8(r);
    } else {
        float xs[8];
        unp8(X04[o], xs);
#pragma unroll
        for (int u = 0; u < 8; u++) xs[u] += r[u];
        X04[o] = pk8(xs);
        float gg[8];
#pragma unroll
        for (int u = 0; u < 8; u++) gg[u] = r[u] + v[u];
        ((uint4*)g_G1)[o] = pk8(gg);
    }
}

// ---------------- SAGE mean aggregation (warp per node, fp16) ----------
__global__ void k_sage(const fp16* __restrict__ feat, const int* __restrict__ rp,
                       const int* __restrict__ col, const float* __restrict__ inv,
                       fp16* __restrict__ out) {
    int node = blockIdx.x * 8 + (threadIdx.x >> 5);
    int lane = threadIdx.x & 31;
    if (node >= NN) return;

    const uint4* f4 = (const uint4*)feat;
    float acc[8] = {0, 0, 0, 0, 0, 0, 0, 0};
    int e0 = rp[node], e1 = rp[node + 1];
    for (int e = e0; e < e1; e++) {
        int s = col[e];
        float f[8];
        unp8(f4[(size_t)s * 32 + lane], f);
#pragma unroll
        for (int u = 0; u < 8; u++) acc[u] += f[u];
    }
    float ic = inv[node];
#pragma unroll
    for (int u = 0; u < 8; u++) acc[u] *= ic;
    ((uint4*)out)[(size_t)node * 32 + lane] = pk8(acc);
}

// ---------------- final reduction ----------------
__global__ void k_final(float* out) {
    __shared__ float s[1024];
    int t = threadIdx.x;
    float v = 0;
    for (int i = t; i < 1564; i += 1024) v += g_part[i];
    s[t] = v;
    __syncthreads();
    for (int off = 512; off; off >>= 1) {
        if (t < off) s[t] += s[t + off];
        __syncthreads();
    }
    if (t == 0) out[0] = s[0] * (1.0f / (2.0f * (float)NN));
}

// ---------------- host ----------------
static void* symaddr(const void* s) {
    void* p = nullptr;
    cudaGetSymbolAddress(&p, s);
    return p;
}

static cudaStream_t mkstream() {
    cudaStream_t s;
    cudaStreamCreateWithFlags(&s, cudaStreamNonBlocking);
    return s;
}
static cudaEvent_t mkevent() {
    cudaEvent_t e;
    cudaEventCreateWithFlags(&e, cudaEventDisableTiming);
    return e;
}

extern "C" void kernel_launch(void* const* d_in, const int* in_sizes, int n_in,
                              void* d_out, int out_size) {
    static cudaStream_t s1 = mkstream();
    static cudaStream_t s2 = mkstream();
    static cudaEvent_t eF = mkevent();
    static cudaEvent_t e1 = mkevent();
    static cudaEvent_t e2 = mkevent();
    static cudaEvent_t eG = mkevent();
    static cudaEvent_t eB = mkevent();

    const float* x   = (const float*)d_in[0];
    const float* x1  = (const float*)d_in[1];
    const int*   ei  = (const int*)d_in[2];
    const int*   ei1 = (const int*)d_in[3];
    const float* Wg1 = (const float*)d_in[4];
    const float* bg1 = (const float*)d_in[5];
    const float* Wg2 = (const float*)d_in[6];
    const float* bg2 = (const float*)d_in[7];
    const float* Wl1 = (const float*)d_in[8];
    const float* bl1 = (const float*)d_in[9];
    const float* Wr1 = (const float*)d_in[10];
    const float* Wl2 = (const float*)d_in[11];
    const float* bl2 = (const float*)d_in[12];
    const float* Wr2 = (const float*)d_in[13];
    const float* Wm1 = (const float*)d_in[14];
    const float* bm1 = (const float*)d_in[15];
    const float* lnw = (const float*)d_in[16];
    const float* lnb = (const float*)d_in[17];
    const float* Wm2 = (const float*)d_in[18];
    const float* bm2 = (const float*)d_in[19];

    const int* src1 = ei;
    const int* dst1 = ei + EE;
    const int* src2 = ei1;
    const int* dst2 = ei1 + EE;

    fp16* XW1  = (fp16*)symaddr(g_XW1);
    fp16* XW2  = (fp16*)symaddr(g_XW2);
    fp16* X0   = (fp16*)symaddr(g_X0);
    fp16* G1   = (fp16*)symaddr(g_G1);
    fp16* MEAN = (fp16*)symaddr(g_MEAN);
    fp16* A1   = (fp16*)symaddr(g_A1);
    float* dis1 = (float*)symaddr(g_dis1);
    float* dis2 = (float*)symaddr(g_dis2);
    float* inv1 = (float*)symaddr(g_inv1);
    float* inv2 = (float*)symaddr(g_inv2);
    int* deg1 = (int*)symaddr(g_deg1);
    int* deg2 = (int*)symaddr(g_deg2);
    int* rp1  = (int*)symaddr(g_rp1);
    int* rp2  = (int*)symaddr(g_rp2);
    int* cur1 = (int*)symaddr(g_cur1);
    int* cur2 = (int*)symaddr(g_cur2);
    int* col1 = (int*)symaddr(g_col1);
    int* col2 = (int*)symaddr(g_col2);
    fp16* wt = (fp16*)symaddr(g_wt);

    fp16* MEANB = XW1;   // branch-B reuse
    fp16* A1B   = XW2;

    const int TB = 256;
    const int gN = (NN + TB - 1) / TB;
    const int gE = (EE + TB - 1) / TB;

    cudaFuncSetAttribute(k_mma<true, false>,  cudaFuncAttributeMaxDynamicSharedMemorySize, SMEM_MMA);
    cudaFuncSetAttribute(k_mma<false, false>, cudaFuncAttributeMaxDynamicSharedMemorySize, SMEM_MMA);
    cudaFuncSetAttribute(k_mma<false, true>,  cudaFuncAttributeMaxDynamicSharedMemorySize, SMEM_MMA);
    const int GY = (NN + 127) / 128;  // 782
    dim3 g256(HH / 128, GY);
    dim3 g128(HG / 128, GY);
    const int gW = NN / 8;

    // ---- fork ----
    cudaEventRecord(eF, 0);
    cudaStreamWaitEvent(s1, eF, 0);
    cudaStreamWaitEvent(s2, eF, 0);

    // ---- s0: graph-1 GCN GEMM (fp32 A fused conversion) ----
    k_wt<<<(FF * HH + 255) / 256, 256, 0, 0>>>(Wg1, wt + OWG1, FF, HH);
    k_mma<true, false><<<g256, 256, SMEM_MMA, 0>>>(
        x, wt + OWG1, FF, nullptr, nullptr, 0, XW1, HH, nullptr, 0,
        nullptr, nullptr, nullptr, nullptr, 0);

    // ---- s1: graph-2 GCN GEMM ----
    k_wt<<<(FF * HH + 255) / 256, 256, 0, s1>>>(Wg2, wt + OWG2, FF, HH);
    k_mma<true, false><<<g256, 256, SMEM_MMA, s1>>>(
        x1, wt + OWG2, FF, nullptr, nullptr, 0, XW2, HH, nullptr, 0,
        nullptr, nullptr, nullptr, nullptr, 0);
    cudaEventRecord(e1, s1);

    // ---- s2: CSR build + SAGE/MLP weight transposes ----
    k_wt<<<(HH * HG + 255) / 256, 256, 0, s2>>>(Wl1, wt + OWL1, HH, HG);
    k_wt<<<(HH * HG + 255) / 256, 256, 0, s2>>>(Wr1, wt + OWR1, HH, HG);
    k_wt<<<(HH * HG + 255) / 256, 256, 0, s2>>>(Wl2, wt + OWL2, HH, HG);
    k_wt<<<(HH * HG + 255) / 256, 256, 0, s2>>>(Wr2, wt + OWR2, HH, HG);
    k_wt<<<(HG * HG + 255) / 256, 256, 0, s2>>>(Wm1, wt + OWM1, HG, HG);
    k_zero_int<<<gN, TB, 0, s2>>>(deg1, NN);
    k_zero_int<<<gN, TB, 0, s2>>>(deg2, NN);
    k_deg<<<gE, TB, 0, s2>>>(dst1, deg1);
    k_deg<<<gE, TB, 0, s2>>>(dst2, deg2);
    k_scan<<<1, 1024, 0, s2>>>(deg1, rp1, NN);
    k_scan<<<1, 1024, 0, s2>>>(deg2, rp2, NN);
    k_disinv<<<gN, TB, 0, s2>>>(deg1, dis1, inv1);
    k_disinv<<<gN, TB, 0, s2>>>(deg2, dis2, inv2);
    k_copy_int<<<gN, TB, 0, s2>>>(cur1, rp1, NN);
    k_copy_int<<<gN, TB, 0, s2>>>(cur2, rp2, NN);
    k_place<<<gE, TB, 0, s2>>>(src1, dst1, cur1, col1);
    k_place<<<gE, TB, 0, s2>>>(src2, dst2, cur2, col2);
    cudaEventRecord(e2, s2);

    // ---- s0: GCN aggregations (serial RMW on X0) ----
    cudaStreamWaitEvent(0, e2, 0);
    k_gcn<<<gW, 256, 0, 0>>>(XW1, rp1, col1, dis1, bg1, 0);
    cudaStreamWaitEvent(0, e1, 0);
    k_gcn<<<gW, 256, 0, 0>>>(XW2, rp2, col2, dis2, bg2, 1);
    cudaEventRecord(eG, 0);

    // ---- branch A on s0 ----
    k_sage<<<gW, 256, 0, 0>>>(X0, rp1, col1, inv1, MEAN);
    k_mma<false, false><<<g128, 256, SMEM_MMA, 0>>>(
        MEAN, wt + OWL1, HH, X0, wt + OWR1, HH, A1, HG, bl1, 1,
        nullptr, nullptr, nullptr, nullptr, 0);
    k_mma<false, true><<<g128, 256, SMEM_MMA, 0>>>(
        A1, wt + OWM1, HG, nullptr, nullptr, 0, nullptr, HG, bm1, 0,
        lnw, lnb, Wm2, bm2, 0);

    // ---- branch B on s1 ----
    cudaStreamWaitEvent(s1, eG, 0);
    k_sage<<<gW, 256, 0, s1>>>(G1, rp2, col2, inv2, MEANB);
    k_mma<false, false><<<g128, 256, SMEM_MMA, s1>>>(
        MEANB, wt + OWL2, HH, G1, wt + OWR2, HH, A1B, HG, bl2, 1,
        nullptr, nullptr, nullptr, nullptr, 0);
    k_mma<false, true><<<g128, 256, SMEM_MMA, s1>>>(
        A1B, wt + OWM1, HG, nullptr, nullptr, 0, nullptr, HG, bm1, 0,
        lnw, lnb, Wm2, bm2, 782);
    cudaEventRecord(eB, s1);

    // ---- join + final reduction ----
    cudaStreamWaitEvent(0, eB, 0);
    k_final<<<1, 1024, 0, 0>>>((float*)d_out);
}

// round 8
// speedup vs baseline: 3.8242x; 1.0188x over previous
#include <cuda_runtime.h>
#include <cuda_fp16.h>
#include <cstdint>

#define NN 100000
#define EE 600000
#define FF 512
#define HH 256
#define HG 128   // H2

typedef __half fp16;
typedef __half2 fp162;

// ---------------- scratch (static __device__ — no allocations) ----------------
__device__ fp16 g_XW1[(size_t)NN * HH];   // later reused as branch-B MEAN
__device__ fp16 g_XW2[(size_t)NN * HH];   // later reused as branch-B A1
__device__ fp16 g_X0 [(size_t)NN * HH];
__device__ fp16 g_G1 [(size_t)NN * HH];
__device__ fp16 g_MEAN[(size_t)NN * HH];  // branch-A MEAN
__device__ fp16 g_A1 [(size_t)NN * HG];   // branch-A A1
__device__ float g_dis1[NN], g_dis2[NN], g_inv1[NN], g_inv2[NN];
__device__ int   g_deg1[NN], g_deg2[NN];
__device__ int   g_rp1[NN + 1], g_rp2[NN + 1];
__device__ int   g_cur1[NN + 1], g_cur2[NN + 1];
__device__ int   g_col1[EE], g_col2[EE];
__device__ float g_part[1600];

// pre-transposed fp16 weights, layout WT[n*K + k]
#define OWG1 0
#define OWG2 131072
#define OWL1 262144
#define OWR1 294912
#define OWL2 327680
#define OWR2 360448
#define OWM1 393216
__device__ fp16 g_wt[409600];

// ---------------- weight transpose ----------------
__global__ void k_wt(const float* __restrict__ W, fp16* __restrict__ th, int K, int M) {
    int i = blockIdx.x * blockDim.x + threadIdx.x;
    if (i < K * M) {
        int k = i / M, n = i % M;
        th[(size_t)n * K + k] = __float2half(W[i]);
    }
}

// ---------------- MMA GEMM ----------------
#define LDSB 80          // bytes per smem row (32 fp16 = 64B + 16B pad)
#define STG_T 10240      // 128 rows * 80B
#define OFF_A  0
#define OFF_B  30720     // 3 A stages
#define SMEM_MMA 61440   // 3 stages * (A + B)

__device__ __forceinline__ void cpa16(uint32_t dst, const void* src) {
    asm volatile("cp.async.ca.shared.global [%0], [%1], 16;"
                 :: "r"(dst), "l"(src));
}

__device__ __forceinline__ void mma_fp16(float* c, const uint32_t* a, const uint32_t* b) {
    asm volatile(
        "mma.sync.aligned.m16n8k16.row.col.f32.f16.f16.f32 "
        "{%0,%1,%2,%3}, {%4,%5,%6,%7}, {%8,%9}, {%0,%1,%2,%3};"
        : "+f"(c[0]), "+f"(c[1]), "+f"(c[2]), "+f"(c[3])
        : "r"(a[0]), "r"(a[1]), "r"(a[2]), "r"(a[3]), "r"(b[0]), "r"(b[1]));
}

__device__ __forceinline__ uint32_t pkh(float a, float b) {
    fp162 h = __float22half2_rn(make_float2(a, b));
    return *(uint32_t*)&h;
}

// A32: A1v is fp32, converted in-kernel (A2 unused). LN: fused LayerNorm+dot epilogue.
template<bool A32, bool LN>
__global__ void __launch_bounds__(256, 2)
k_mma(const void* __restrict__ A1v, const fp16* __restrict__ W1, int K1,
      const fp16* __restrict__ A2p, const fp16* __restrict__ W2, int K2,
      fp16* __restrict__ C, int M,
      const float* __restrict__ bias, int reluflag,
      const float* __restrict__ lnw, const float* __restrict__ lnb,
      const float* __restrict__ wm2, const float* __restrict__ bm2, int poff)
{
    extern __shared__ __align__(16) char smem[];
    const uint32_t sb = (uint32_t)__cvta_generic_to_shared(smem);
    const int tid = threadIdx.x;
    const int wid = tid >> 5, lane = tid & 31;
    const int warp_m = wid & 1, warp_n = wid >> 1;
    const int rowBase = blockIdx.y * 128;
    const int colBase = blockIdx.x * 128;

    const int n1 = K1 >> 5;
    const int n2 = A2p ? (K2 >> 5) : 0;
    const int total = n1 + n2;

    float acc[4][4][4];
#pragma unroll
    for (int i = 0; i < 4; i++)
#pragma unroll
        for (int j = 0; j < 4; j++)
#pragma unroll
            for (int q = 0; q < 4; q++) acc[i][j][q] = 0.0f;

    uint32_t aregs[8];

    auto pick = [&](int it, const fp16*& A, const fp16*& W, int& K, int& k0) {
        if (it < n1) { A = (const fp16*)A1v; W = W1; K = K1; k0 = it << 5; }
        else         { A = A2p; W = W2; K = K2; k0 = (it - n1) << 5; }
    };

    auto issue = [&](int it, int stage) {
        const fp16 *A, *W; int K, k0;
        pick(it, A, W, K, k0);
        if (!A32) {
#pragma unroll
            for (int i = 0; i < 2; i++) {
                int idx = tid + i * 256;
                int r = idx >> 2, part = idx & 3;
                int gr = rowBase + r;
                uint32_t d = sb + OFF_A + stage * STG_T + r * LDSB + part * 16;
                if (gr < NN) cpa16(d, A + (size_t)gr * K + k0 + part * 8);
                else asm volatile("st.shared.v4.b32 [%0], {%1,%1,%1,%1};" :: "r"(d), "r"(0));
            }
        }
#pragma unroll
        for (int i = 0; i < 2; i++) {
            int idx = tid + i * 256;
            int n = idx >> 2, part = idx & 3;
            int gn = colBase + n;
            uint32_t d = sb + OFF_B + stage * STG_T + n * LDSB + part * 16;
            cpa16(d, W + (size_t)gn * K + k0 + part * 8);
        }
        asm volatile("cp.async.commit_group;");
    };

    auto loadAreg = [&](int it) {
        if (A32) {
            const float* Af = (const float*)A1v;
            int k0 = it << 5;
            int gr = rowBase + (tid >> 1);
            const float* p = Af + (size_t)gr * K1 + k0 + (tid & 1) * 16;
#pragma unroll
            for (int j = 0; j < 4; j++) {
                float4 v = (gr < NN) ? *(const float4*)(p + 4 * j)
                                     : make_float4(0.f, 0.f, 0.f, 0.f);
                aregs[2 * j] = pkh(v.x, v.y);
                aregs[2 * j + 1] = pkh(v.z, v.w);
            }
        }
    };

    auto storeAreg = [&](int stage) {
        if (A32) {
            uint32_t d = sb + OFF_A + stage * STG_T + (tid >> 1) * LDSB + (tid & 1) * 32;
            asm volatile("st.shared.v4.b32 [%0], {%1,%2,%3,%4};"
                         :: "r"(d), "r"(aregs[0]), "r"(aregs[1]),
                            "r"(aregs[2]), "r"(aregs[3]));
            asm volatile("st.shared.v4.b32 [%0], {%1,%2,%3,%4};"
                         :: "r"(d + 16), "r"(aregs[4]), "r"(aregs[5]),
                            "r"(aregs[6]), "r"(aregs[7]));
        }
    };

    auto compute = [&](int stage) {
#pragma unroll
        for (int ks = 0; ks < 2; ks++) {
            const int kk = ks * 16;
            uint32_t af[4][4];
#pragma unroll
            for (int mi = 0; mi < 4; mi++) {
                int row = warp_m * 64 + mi * 16 + (lane & 15);
                int kc = kk + ((lane >> 4) << 3);
                uint32_t ad = sb + OFF_A + stage * STG_T + row * LDSB + kc * 2;
                asm volatile("ldmatrix.sync.aligned.m8n8.x4.shared.b16 "
                             "{%0,%1,%2,%3}, [%4];"
                             : "=r"(af[mi][0]), "=r"(af[mi][1]),
                               "=r"(af[mi][2]), "=r"(af[mi][3]) : "r"(ad));
            }
            uint32_t bh[4][2];
#pragma unroll
            for (int pair = 0; pair < 2; pair++) {
                int rn = warp_n * 32 + pair * 16 + ((lane >> 4) << 3) + (lane & 7);
                int kc = kk + ((lane >> 3) & 1) * 8;
                uint32_t off = sb + OFF_B + stage * STG_T + rn * LDSB + kc * 2;
                asm volatile("ldmatrix.sync.aligned.m8n8.x4.shared.b16 "
                             "{%0,%1,%2,%3}, [%4];"
                             : "=r"(bh[2 * pair][0]), "=r"(bh[2 * pair][1]),
                               "=r"(bh[2 * pair + 1][0]), "=r"(bh[2 * pair + 1][1])
                             : "r"(off));
            }
#pragma unroll
            for (int mi = 0; mi < 4; mi++)
#pragma unroll
                for (int ni = 0; ni < 4; ni++)
                    mma_fp16(acc[mi][ni], af[mi], bh[ni]);
        }
    };

    // ---- prologue: prime 2 stages ----
    issue(0, 0);
    loadAreg(0);
    storeAreg(0);
    if (total > 1) {
        issue(1, 1);
        loadAreg(1);
        storeAreg(1);
    }

    // ---- 3-stage pipelined mainloop ----
    for (int it = 0; it < total; ++it) {
        const int stage = it % 3;
        if (it + 1 < total) asm volatile("cp.async.wait_group 1;");
        else               asm volatile("cp.async.wait_group 0;");
        __syncthreads();
        if (it + 2 < total) {
            issue(it + 2, (it + 2) % 3);
            loadAreg(it + 2);
            storeAreg((it + 2) % 3);
        }
        compute(stage);
    }

    const int g = lane >> 2, tg = lane & 3;

    if (!LN) {
        // ---- normal epilogue: fp16 out ----
#pragma unroll
        for (int mi = 0; mi < 4; mi++) {
#pragma unroll
            for (int ni = 0; ni < 4; ni++) {
                int col = colBase + warp_n * 32 + ni * 8 + tg * 2;
                float b0 = 0.f, b1 = 0.f;
                if (bias) { b0 = bias[col]; b1 = bias[col + 1]; }
                int row = rowBase + warp_m * 64 + mi * 16 + g;
                if (row < NN) {
                    float vx = acc[mi][ni][0] + b0, vy = acc[mi][ni][1] + b1;
                    if (reluflag) { vx = fmaxf(vx, 0.f); vy = fmaxf(vy, 0.f); }
                    fp162 h = __float22half2_rn(make_float2(vx, vy));
                    *(fp162*)(C + (size_t)row * M + col) = h;
                }
                if (row + 8 < NN) {
                    float vx = acc[mi][ni][2] + b0, vy = acc[mi][ni][3] + b1;
                    if (reluflag) { vx = fmaxf(vx, 0.f); vy = fmaxf(vy, 0.f); }
                    fp162 h = __float22half2_rn(make_float2(vx, vy));
                    *(fp162*)(C + (size_t)(row + 8) * M + col) = h;
                }
            }
        }
    } else {
        // ---- fused LayerNorm + dot(wm2) epilogue (M=128, gridDim.x=1) ----
        __syncthreads();
        float* sred = (float*)smem;             // [128][8]
        float* sdot = (float*)(smem + 4096);    // [128][4]
        float* sblk = (float*)(smem + 6144);    // [4]

        float b0[4], b1[4], w0[4], w1[4], l0[4], l1[4], m0[4], m1[4];
#pragma unroll
        for (int ni = 0; ni < 4; ni++) {
            int c = warp_n * 32 + ni * 8 + tg * 2;
            b0[ni] = bias[c];  b1[ni] = bias[c + 1];
            w0[ni] = lnw[c];   w1[ni] = lnw[c + 1];
            l0[ni] = lnb[c];   l1[ni] = lnb[c + 1];
            m0[ni] = wm2[c];   m1[ni] = wm2[c + 1];
        }

        // pass 1: row partial sums
#pragma unroll
        for (int mi = 0; mi < 4; mi++) {
#pragma unroll
            for (int half = 0; half < 2; half++) {
                float ps = 0.f, pq = 0.f;
#pragma unroll
                for (int ni = 0; ni < 4; ni++) {
                    float v = acc[mi][ni][half * 2] + b0[ni];
                    float u = acc[mi][ni][half * 2 + 1] + b1[ni];
                    ps += v + u;
                    pq += v * v + u * u;
                }
                ps += __shfl_xor_sync(0xffffffffu, ps, 1);
                ps += __shfl_xor_sync(0xffffffffu, ps, 2);
                pq += __shfl_xor_sync(0xffffffffu, pq, 1);
                pq += __shfl_xor_sync(0xffffffffu, pq, 2);
                int r = warp_m * 64 + mi * 16 + g + half * 8;
                if (tg == 0) {
                    sred[r * 8 + warp_n * 2] = ps;
                    sred[r * 8 + warp_n * 2 + 1] = pq;
                }
            }
        }
        __syncthreads();

        // pass 2: normalize + dot
#pragma unroll
        for (int mi = 0; mi < 4; mi++) {
#pragma unroll
            for (int half = 0; half < 2; half++) {
                int r = warp_m * 64 + mi * 16 + g + half * 8;
                float sum = sred[r * 8 + 0] + sred[r * 8 + 2] + sred[r * 8 + 4] + sred[r * 8 + 6];
                float sq  = sred[r * 8 + 1] + sred[r * 8 + 3] + sred[r * 8 + 5] + sred[r * 8 + 7];
                float mu = sum * (1.0f / 128.0f);
                float var = sq * (1.0f / 128.0f) - mu * mu;
                float rs = rsqrtf(var + 1e-5f);
                float p = 0.f;
#pragma unroll
                for (int ni = 0; ni < 4; ni++) {
                    float v = acc[mi][ni][half * 2] + b0[ni];
                    float u = acc[mi][ni][half * 2 + 1] + b1[ni];
                    p += ((v - mu) * rs * w0[ni] + l0[ni]) * m0[ni]
                       + ((u - mu) * rs * w1[ni] + l1[ni]) * m1[ni];
                }
                p += __shfl_xor_sync(0xffffffffu, p, 1);
                p += __shfl_xor_sync(0xffffffffu, p, 2);
                if (tg == 0) sdot[r * 4 + warp_n] = p;
            }
        }
        __syncthreads();

        // pass 3: per-CTA partial of sum over valid rows
        if (tid < 128) {
            int r = tid;
            int grow = rowBase + r;
            float y = 0.f;
            if (grow < NN)
                y = sdot[r * 4] + sdot[r * 4 + 1] + sdot[r * 4 + 2] + sdot[r * 4 + 3] + bm2[0];
#pragma unroll
            for (int o = 16; o; o >>= 1) y += __shfl_xor_sync(0xffffffffu, y, o);
            if ((tid & 31) == 0) sblk[tid >> 5] = y;
        }
        __syncthreads();
        if (tid == 0)
            g_part[poff + blockIdx.y] = sblk[0] + sblk[1] + sblk[2] + sblk[3];
    }
}

// ---------------- small utility kernels ----------------
__global__ void k_zero_int(int* p, int n) {
    int i = blockIdx.x * blockDim.x + threadIdx.x;
    if (i < n) p[i] = 0;
}

__global__ void k_copy_int(int* dst, const int* src, int n) {
    int i = blockIdx.x * blockDim.x + threadIdx.x;
    if (i < n) dst[i] = src[i];
}

__global__ void k_deg(const int* __restrict__ dst, int* __restrict__ deg) {
    int e = blockIdx.x * blockDim.x + threadIdx.x;
    if (e < EE) atomicAdd(&deg[dst[e]], 1);
}

__global__ void k_scan(const int* __restrict__ deg, int* __restrict__ rp, int n) {
    __shared__ int s[1024];
    int t = threadIdx.x;
    int chunk = (n + 1023) >> 10;
    int b = t * chunk;
    int e = b + chunk; if (e > n) e = n;
    int local = 0;
    for (int i = b; i < e && i < n; i++) local += deg[i];
    s[t] = local;
    __syncthreads();
    for (int off = 1; off < 1024; off <<= 1) {
        int v = (t >= off) ? s[t - off] : 0;
        __syncthreads();
        s[t] += v;
        __syncthreads();
    }
    int run = (t == 0) ? 0 : s[t - 1];
    for (int i = b; i < e && i < n; i++) { rp[i] = run; run += deg[i]; }
    if (t == 1023) rp[n] = s[1023];
}

__global__ void k_disinv(const int* __restrict__ deg, float* __restrict__ dis,
                         float* __restrict__ inv) {
    int i = blockIdx.x * blockDim.x + threadIdx.x;
    if (i < NN) {
        float d = (float)deg[i];
        dis[i] = rsqrtf(d + 1.0f);
        inv[i] = 1.0f / fmaxf(d, 1.0f);
    }
}

__global__ void k_place(const int* __restrict__ src, const int* __restrict__ dst,
                        int* __restrict__ cur, int* __restrict__ col) {
    int e = blockIdx.x * blockDim.x + threadIdx.x;
    if (e < EE) {
        int d = dst[e];
        int p = atomicAdd(&cur[d], 1);
        col[p] = src[e];
    }
}

// ---------------- helpers for fp16 gather ----------------
__device__ __forceinline__ void unp8(uint4 v, float* f) {
    float2 a = __half22float2(*(fp162*)&v.x);
    float2 b = __half22float2(*(fp162*)&v.y);
    float2 c = __half22float2(*(fp162*)&v.z);
    float2 d = __half22float2(*(fp162*)&v.w);
    f[0] = a.x; f[1] = a.y; f[2] = b.x; f[3] = b.y;
    f[4] = c.x; f[5] = c.y; f[6] = d.x; f[7] = d.y;
}

__device__ __forceinline__ uint4 pk8(const float* f) {
    fp162 a = __float22half2_rn(make_float2(f[0], f[1]));
    fp162 b = __float22half2_rn(make_float2(f[2], f[3]));
    fp162 c = __float22half2_rn(make_float2(f[4], f[5]));
    fp162 d = __float22half2_rn(make_float2(f[6], f[7]));
    return make_uint4(*(uint32_t*)&a, *(uint32_t*)&b, *(uint32_t*)&c, *(uint32_t*)&d);
}

// ---------------- GCN aggregation (warp per node, gather over CSR, fp16) ----------
__global__ void k_gcn(const fp16* __restrict__ xw, const int* __restrict__ rp,
                      const int* __restrict__ col, const float* __restrict__ dis,
                      const float* __restrict__ bias, int mode) {
    int node = blockIdx.x * 8 + (threadIdx.x >> 5);
    int lane = threadIdx.x & 31;
    if (node >= NN) return;

    const uint4* xw4 = (const uint4*)xw;
    float acc[8] = {0, 0, 0, 0, 0, 0, 0, 0};
    int e0 = rp[node], e1 = rp[node + 1];
    for (int e = e0; e < e1; e++) {
        int s = col[e];
        float ds = dis[s];
        float f[8];
        unp8(xw4[(size_t)s * 32 + lane], f);
#pragma unroll
        for (int u = 0; u < 8; u++) acc[u] += f[u] * ds;
    }
    float di = dis[node];
    float dii = di * di;
    float sf[8];
    unp8(xw4[(size_t)node * 32 + lane], sf);
    const float4* b4 = (const float4*)bias;
    float4 bb0 = b4[2 * lane], bb1 = b4[2 * lane + 1];
    float bb[8] = {bb0.x, bb0.y, bb0.z, bb0.w, bb1.x, bb1.y, bb1.z, bb1.w};

    float v[8], r[8];
#pragma unroll
    for (int u = 0; u < 8; u++) {
        v[u] = acc[u] * di + sf[u] * dii + bb[u];
        r[u] = fmaxf(v[u], 0.f);
    }

    size_t o = (size_t)node * 32 + lane;
    uint4* X04 = (uint4*)g_X0;
    if (mode == 0) {
        X04[o] = pk8(r);
    } else {
        float xs[8];
        unp8(X04[o], xs);
#pragma unroll
        for (int u = 0; u < 8; u++) xs[u] += r[u];
        X04[o] = pk8(xs);
        float gg[8];
#pragma unroll
        for (int u = 0; u < 8; u++) gg[u] = r[u] + v[u];
        ((uint4*)g_G1)[o] = pk8(gg);
    }
}

// ---------------- SAGE mean aggregation (warp per node, fp16) ----------
__global__ void k_sage(const fp16* __restrict__ feat, const int* __restrict__ rp,
                       const int* __restrict__ col, const float* __restrict__ inv,
                       fp16* __restrict__ out) {
    int node = blockIdx.x * 8 + (threadIdx.x >> 5);
    int lane = threadIdx.x & 31;
    if (node >= NN) return;

    const uint4* f4 = (const uint4*)feat;
    float acc[8] = {0, 0, 0, 0, 0, 0, 0, 0};
    int e0 = rp[node], e1 = rp[node + 1];
    for (int e = e0; e < e1; e++) {
        int s = col[e];
        float f[8];
        unp8(f4[(size_t)s * 32 + lane], f);
#pragma unroll
        for (int u = 0; u < 8; u++) acc[u] += f[u];
    }
    float ic = inv[node];
#pragma unroll
    for (int u = 0; u < 8; u++) acc[u] *= ic;
    ((uint4*)out)[(size_t)node * 32 + lane] = pk8(acc);
}

// ---------------- final reduction ----------------
__global__ void k_final(float* out) {
    __shared__ float s[1024];
    int t = threadIdx.x;
    float v = 0;
    for (int i = t; i < 1564; i += 1024) v += g_part[i];
    s[t] = v;
    __syncthreads();
    for (int off = 512; off; off >>= 1) {
        if (t < off) s[t] += s[t + off];
        __syncthreads();
    }
    if (t == 0) out[0] = s[0] * (1.0f / (2.0f * (float)NN));
}

// ---------------- host ----------------
static void* symaddr(const void* s) {
    void* p = nullptr;
    cudaGetSymbolAddress(&p, s);
    return p;
}

static cudaStream_t mkstream() {
    cudaStream_t s;
    cudaStreamCreateWithFlags(&s, cudaStreamNonBlocking);
    return s;
}
static cudaEvent_t mkevent() {
    cudaEvent_t e;
    cudaEventCreateWithFlags(&e, cudaEventDisableTiming);
    return e;
}

extern "C" void kernel_launch(void* const* d_in, const int* in_sizes, int n_in,
                              void* d_out, int out_size) {
    static cudaStream_t s1 = mkstream();
    static cudaStream_t s2 = mkstream();
    static cudaEvent_t eF = mkevent();
    static cudaEvent_t e1 = mkevent();
    static cudaEvent_t e2 = mkevent();
    static cudaEvent_t eG = mkevent();
    static cudaEvent_t eB = mkevent();

    const float* x   = (const float*)d_in[0];
    const float* x1  = (const float*)d_in[1];
    const int*   ei  = (const int*)d_in[2];
    const int*   ei1 = (const int*)d_in[3];
    const float* Wg1 = (const float*)d_in[4];
    const float* bg1 = (const float*)d_in[5];
    const float* Wg2 = (const float*)d_in[6];
    const float* bg2 = (const float*)d_in[7];
    const float* Wl1 = (const float*)d_in[8];
    const float* bl1 = (const float*)d_in[9];
    const float* Wr1 = (const float*)d_in[10];
    const float* Wl2 = (const float*)d_in[11];
    const float* bl2 = (const float*)d_in[12];
    const float* Wr2 = (const float*)d_in[13];
    const float* Wm1 = (const float*)d_in[14];
    const float* bm1 = (const float*)d_in[15];
    const float* lnw = (const float*)d_in[16];
    const float* lnb = (const float*)d_in[17];
    const float* Wm2 = (const float*)d_in[18];
    const float* bm2 = (const float*)d_in[19];

    const int* src1 = ei;
    const int* dst1 = ei + EE;
    const int* src2 = ei1;
    const int* dst2 = ei1 + EE;

    fp16* XW1  = (fp16*)symaddr(g_XW1);
    fp16* XW2  = (fp16*)symaddr(g_XW2);
    fp16* X0   = (fp16*)symaddr(g_X0);
    fp16* G1   = (fp16*)symaddr(g_G1);
    fp16* MEAN = (fp16*)symaddr(g_MEAN);
    fp16* A1   = (fp16*)symaddr(g_A1);
    float* dis1 = (float*)symaddr(g_dis1);
    float* dis2 = (float*)symaddr(g_dis2);
    float* inv1 = (float*)symaddr(g_inv1);
    float* inv2 = (float*)symaddr(g_inv2);
    int* deg1 = (int*)symaddr(g_deg1);
    int* deg2 = (int*)symaddr(g_deg2);
    int* rp1  = (int*)symaddr(g_rp1);
    int* rp2  = (int*)symaddr(g_rp2);
    int* cur1 = (int*)symaddr(g_cur1);
    int* cur2 = (int*)symaddr(g_cur2);
    int* col1 = (int*)symaddr(g_col1);
    int* col2 = (int*)symaddr(g_col2);
    fp16* wt = (fp16*)symaddr(g_wt);

    fp16* MEANB = XW1;   // branch-B reuse
    fp16* A1B   = XW2;

    const int TB = 256;
    const int gN = (NN + TB - 1) / TB;
    const int gE = (EE + TB - 1) / TB;

    cudaFuncSetAttribute(k_mma<true, false>,  cudaFuncAttributeMaxDynamicSharedMemorySize, SMEM_MMA);
    cudaFuncSetAttribute(k_mma<false, false>, cudaFuncAttributeMaxDynamicSharedMemorySize, SMEM_MMA);
    cudaFuncSetAttribute(k_mma<false, true>,  cudaFuncAttributeMaxDynamicSharedMemorySize, SMEM_MMA);
    const int GY = (NN + 127) / 128;  // 782
    dim3 g256(HH / 128, GY);
    dim3 g128(HG / 128, GY);
    const int gW = NN / 8;

    // ---- fork ----
    cudaEventRecord(eF, 0);
    cudaStreamWaitEvent(s1, eF, 0);
    cudaStreamWaitEvent(s2, eF, 0);

    // ---- s0: graph-1 GCN GEMM (fp32 A fused conversion) ----
    k_wt<<<(FF * HH + 255) / 256, 256, 0, 0>>>(Wg1, wt + OWG1, FF, HH);
    k_mma<true, false><<<g256, 256, SMEM_MMA, 0>>>(
        x, wt + OWG1, FF, nullptr, nullptr, 0, XW1, HH, nullptr, 0,
        nullptr, nullptr, nullptr, nullptr, 0);

    // ---- s1: graph-2 GCN GEMM ----
    k_wt<<<(FF * HH + 255) / 256, 256, 0, s1>>>(Wg2, wt + OWG2, FF, HH);
    k_mma<true, false><<<g256, 256, SMEM_MMA, s1>>>(
        x1, wt + OWG2, FF, nullptr, nullptr, 0, XW2, HH, nullptr, 0,
        nullptr, nullptr, nullptr, nullptr, 0);
    cudaEventRecord(e1, s1);

    // ---- s2: CSR build + SAGE/MLP weight transposes ----
    k_wt<<<(HH * HG + 255) / 256, 256, 0, s2>>>(Wl1, wt + OWL1, HH, HG);
    k_wt<<<(HH * HG + 255) / 256, 256, 0, s2>>>(Wr1, wt + OWR1, HH, HG);
    k_wt<<<(HH * HG + 255) / 256, 256, 0, s2>>>(Wl2, wt + OWL2, HH, HG);
    k_wt<<<(HH * HG + 255) / 256, 256, 0, s2>>>(Wr2, wt + OWR2, HH, HG);
    k_wt<<<(HG * HG + 255) / 256, 256, 0, s2>>>(Wm1, wt + OWM1, HG, HG);
    k_zero_int<<<gN, TB, 0, s2>>>(deg1, NN);
    k_zero_int<<<gN, TB, 0, s2>>>(deg2, NN);
    k_deg<<<gE, TB, 0, s2>>>(dst1, deg1);
    k_deg<<<gE, TB, 0, s2>>>(dst2, deg2);
    k_scan<<<1, 1024, 0, s2>>>(deg1, rp1, NN);
    k_scan<<<1, 1024, 0, s2>>>(deg2, rp2, NN);
    k_disinv<<<gN, TB, 0, s2>>>(deg1, dis1, inv1);
    k_disinv<<<gN, TB, 0, s2>>>(deg2, dis2, inv2);
    k_copy_int<<<gN, TB, 0, s2>>>(cur1, rp1, NN);
    k_copy_int<<<gN, TB, 0, s2>>>(cur2, rp2, NN);
    k_place<<<gE, TB, 0, s2>>>(src1, dst1, cur1, col1);
    k_place<<<gE, TB, 0, s2>>>(src2, dst2, cur2, col2);
    cudaEventRecord(e2, s2);

    // ---- s0: GCN aggregations (serial RMW on X0) ----
    cudaStreamWaitEvent(0, e2, 0);
    k_gcn<<<gW, 256, 0, 0>>>(XW1, rp1, col1, dis1, bg1, 0);
    cudaStreamWaitEvent(0, e1, 0);
    k_gcn<<<gW, 256, 0, 0>>>(XW2, rp2, col2, dis2, bg2, 1);
    cudaEventRecord(eG, 0);

    // ---- branch A on s0 ----
    k_sage<<<gW, 256, 0, 0>>>(X0, rp1, col1, inv1, MEAN);
    k_mma<false, false><<<g128, 256, SMEM_MMA, 0>>>(
        MEAN, wt + OWL1, HH, X0, wt + OWR1, HH, A1, HG, bl1, 1,
        nullptr, nullptr, nullptr, nullptr, 0);
    k_mma<false, true><<<g128, 256, SMEM_MMA, 0>>>(
        A1, wt + OWM1, HG, nullptr, nullptr, 0, nullptr, HG, bm1, 0,
        lnw, lnb, Wm2, bm2, 0);

    // ---- branch B on s1 ----
    cudaStreamWaitEvent(s1, eG, 0);
    k_sage<<<gW, 256, 0, s1>>>(G1, rp2, col2, inv2, MEANB);
    k_mma<false, false><<<g128, 256, SMEM_MMA, s1>>>(
        MEANB, wt + OWL2, HH, G1, wt + OWR2, HH, A1B, HG, bl2, 1,
        nullptr, nullptr, nullptr, nullptr, 0);
    k_mma<false, true><<<g128, 256, SMEM_MMA, s1>>>(
        A1B, wt + OWM1, HG, nullptr, nullptr, 0, nullptr, HG, bm1, 0,
        lnw, lnb, Wm2, bm2, 782);
    cudaEventRecord(eB, s1);

    // ---- join + final reduction ----
    cudaStreamWaitEvent(0, eB, 0);
    k_final<<<1, 1024, 0, 0>>>((float*)d_out);
}